// round 1
// baseline (speedup 1.0000x reference)
#include <cuda_runtime.h>
#include <cuda_bf16.h>

// Problem constants: B=32, N=1024, C=128, L=4
#define BB 32
#define NN 1024
#define CC 128
#define LL 4
#define ROWS (BB * NN)          // 32768
#define HSZ  (ROWS * CC)        // 4,194,304 floats
#define GSZ  (ROWS * 3 * CC)    // 12,582,912 floats

// Scratch (device globals: allocation-free, graph-capturable)
__device__ __align__(16) float g_h0[HSZ];
__device__ __align__(16) float g_h1[HSZ];
__device__ __align__(16) float g_hw[HSZ];
__device__ __align__(16) float g_m [HSZ];
__device__ __align__(16) float g_gx[GSZ];
__device__ __align__(16) float g_gh[GSZ];

// ---------------------------------------------------------------------------
// Tiled SGEMM: C[m,n] = sum_k opA(A)[m,k] * opB(B)[k,n]  (+ bias[n])
//   AMODE 0: A row-major          a[m*lda + k]
//   AMODE 1: A k-major (adj^T)    a[k*lda + m]
//   BMODE 0: B k-major            b[k*ldb + n]
//   BMODE 1: B n-major (W^T)      b[n*ldb + k]
// Tile: BM=BN=128, BK=16; 256 threads, 8x8 micro-tile per thread.
// All dims assumed multiples of tile sizes (true for this problem).
// ---------------------------------------------------------------------------
template <int AMODE, int BMODE>
__global__ __launch_bounds__(256)
void sgemm_tile(const float* __restrict__ A, const float* __restrict__ B,
                float* __restrict__ C,
                int M, int N, int K, int lda, int ldb, int ldc,
                long sA, long sB, long sC,
                const float* __restrict__ bias)
{
    __shared__ float As[16][128];
    __shared__ float Bs[16][128];

    const int t  = threadIdx.x;
    const int tx = t & 15;
    const int ty = t >> 4;
    const int m0 = blockIdx.y * 128;
    const int n0 = blockIdx.x * 128;

    A += (long)blockIdx.z * sA;
    B += (long)blockIdx.z * sB;
    C += (long)blockIdx.z * sC;

    float acc[8][8];
    #pragma unroll
    for (int i = 0; i < 8; i++)
        #pragma unroll
        for (int j = 0; j < 8; j++)
            acc[i][j] = 0.0f;

    for (int k0 = 0; k0 < K; k0 += 16) {
        // ---- load A tile into As[k][m] ----
        if (AMODE == 0) {
            const int row = t >> 2;      // 0..63
            const int cv  = t & 3;       // float4 index within 16 cols
            #pragma unroll
            for (int r = 0; r < 2; r++) {
                float4 v = *reinterpret_cast<const float4*>(
                    &A[(long)(m0 + row + r * 64) * lda + k0 + cv * 4]);
                As[cv * 4 + 0][row + r * 64] = v.x;
                As[cv * 4 + 1][row + r * 64] = v.y;
                As[cv * 4 + 2][row + r * 64] = v.z;
                As[cv * 4 + 3][row + r * 64] = v.w;
            }
        } else {
            const int kr = t >> 5;       // 0..7
            const int mv = t & 31;       // float4 index within 128
            #pragma unroll
            for (int r = 0; r < 2; r++) {
                float4 v = *reinterpret_cast<const float4*>(
                    &A[(long)(k0 + kr + r * 8) * lda + m0 + mv * 4]);
                *reinterpret_cast<float4*>(&As[kr + r * 8][mv * 4]) = v;
            }
        }
        // ---- load B tile into Bs[k][n] ----
        if (BMODE == 0) {
            const int kr = t >> 5;
            const int nv = t & 31;
            #pragma unroll
            for (int r = 0; r < 2; r++) {
                float4 v = *reinterpret_cast<const float4*>(
                    &B[(long)(k0 + kr + r * 8) * ldb + n0 + nv * 4]);
                *reinterpret_cast<float4*>(&Bs[kr + r * 8][nv * 4]) = v;
            }
        } else {
            const int row = t >> 2;
            const int cv  = t & 3;
            #pragma unroll
            for (int r = 0; r < 2; r++) {
                float4 v = *reinterpret_cast<const float4*>(
                    &B[(long)(n0 + row + r * 64) * ldb + k0 + cv * 4]);
                Bs[cv * 4 + 0][row + r * 64] = v.x;
                Bs[cv * 4 + 1][row + r * 64] = v.y;
                Bs[cv * 4 + 2][row + r * 64] = v.z;
                Bs[cv * 4 + 3][row + r * 64] = v.w;
            }
        }
        __syncthreads();

        // ---- compute ----
        #pragma unroll
        for (int kk = 0; kk < 16; kk++) {
            float a[8], b[8];
            *reinterpret_cast<float4*>(&a[0]) =
                *reinterpret_cast<const float4*>(&As[kk][ty * 8]);
            *reinterpret_cast<float4*>(&a[4]) =
                *reinterpret_cast<const float4*>(&As[kk][ty * 8 + 4]);
            *reinterpret_cast<float4*>(&b[0]) =
                *reinterpret_cast<const float4*>(&Bs[kk][tx * 8]);
            *reinterpret_cast<float4*>(&b[4]) =
                *reinterpret_cast<const float4*>(&Bs[kk][tx * 8 + 4]);
            #pragma unroll
            for (int i = 0; i < 8; i++)
                #pragma unroll
                for (int j = 0; j < 8; j++)
                    acc[i][j] = fmaf(a[i], b[j], acc[i][j]);
        }
        __syncthreads();
    }

    // ---- epilogue ----
    float bv[8];
    #pragma unroll
    for (int j = 0; j < 8; j++)
        bv[j] = bias ? bias[n0 + tx * 8 + j] : 0.0f;

    #pragma unroll
    for (int i = 0; i < 8; i++) {
        const long crow = (long)(m0 + ty * 8 + i) * ldc + n0 + tx * 8;
        float4 v0, v1;
        v0.x = acc[i][0] + bv[0]; v0.y = acc[i][1] + bv[1];
        v0.z = acc[i][2] + bv[2]; v0.w = acc[i][3] + bv[3];
        v1.x = acc[i][4] + bv[4]; v1.y = acc[i][5] + bv[5];
        v1.z = acc[i][6] + bv[6]; v1.w = acc[i][7] + bv[7];
        *reinterpret_cast<float4*>(&C[crow])     = v0;
        *reinterpret_cast<float4*>(&C[crow + 4]) = v1;
    }
}

// ---------------------------------------------------------------------------
// Fused GRU elementwise: h_new = (1-z)*n + z*h  (PyTorch gate order r,z,n)
// gx/gh are [ROWS, 3*CC] with biases already added by the GEMMs.
// ---------------------------------------------------------------------------
__global__ __launch_bounds__(256)
void gru_elem(const float* __restrict__ gx, const float* __restrict__ gh,
              const float* __restrict__ h, float* __restrict__ hout,
              const float* __restrict__ mask, int applyMask)
{
    const int idx = blockIdx.x * blockDim.x + threadIdx.x;  // < ROWS*CC
    const int r = idx >> 7;       // row (b*N + n)
    const int c = idx & 127;      // channel

    const long gbase = (long)r * (3 * CC);
    const float xr = gx[gbase + c];
    const float xz = gx[gbase + CC + c];
    const float xn = gx[gbase + 2 * CC + c];
    const float hr = gh[gbase + c];
    const float hz = gh[gbase + CC + c];
    const float hn = gh[gbase + 2 * CC + c];

    const float rg = 1.0f / (1.0f + __expf(-(xr + hr)));
    const float zg = 1.0f / (1.0f + __expf(-(xz + hz)));
    const float ng = tanhf(xn + rg * hn);
    float hnew = (1.0f - zg) * ng + zg * h[idx];
    if (applyMask) hnew *= mask[r];
    hout[idx] = hnew;
}

// ---------------------------------------------------------------------------
extern "C" void kernel_launch(void* const* d_in, const int* in_sizes, int n_in,
                              void* d_out, int out_size)
{
    const float* x      = (const float*)d_in[0];  // [B,N,C]
    const float* adj    = (const float*)d_in[1];  // [B,N,N]
    const float* mask   = (const float*)d_in[2];  // [B,N]
    const float* weight = (const float*)d_in[3];  // [L,C,C]
    const float* w_ih   = (const float*)d_in[4];  // [L,3C,C]
    const float* w_hh   = (const float*)d_in[5];  // [L,3C,C]
    const float* b_ih   = (const float*)d_in[6];  // [L,3C]
    const float* b_hh   = (const float*)d_in[7];  // [L,3C]
    float* out = (float*)d_out;

    float *p_h0, *p_h1, *p_hw, *p_m, *p_gx, *p_gh;
    cudaGetSymbolAddress((void**)&p_h0, g_h0);
    cudaGetSymbolAddress((void**)&p_h1, g_h1);
    cudaGetSymbolAddress((void**)&p_hw, g_hw);
    cudaGetSymbolAddress((void**)&p_m,  g_m);
    cudaGetSymbolAddress((void**)&p_gx, g_gx);
    cudaGetSymbolAddress((void**)&p_gh, g_gh);

    float* hbuf[2] = { p_h0, p_h1 };

    for (int l = 0; l < LL; l++) {
        const float* hin  = (l == 0) ? x : hbuf[(l + 1) & 1];
        float*       hout = (l == LL - 1) ? out : hbuf[l & 1];

        // 1) hw = h @ W[l]   (M=32768, N=128, K=128)
        sgemm_tile<0, 0><<<dim3(1, ROWS / 128, 1), 256>>>(
            hin, weight + (long)l * CC * CC, p_hw,
            ROWS, CC, CC, CC, CC, CC, 0, 0, 0, nullptr);

        // 2) m[b] = adj[b]^T @ hw[b]   (batched: M=1024, N=128, K=1024)
        sgemm_tile<1, 0><<<dim3(1, NN / 128, BB), 256>>>(
            adj, p_hw, p_m,
            NN, CC, NN, NN, CC, CC,
            (long)NN * NN, (long)NN * CC, (long)NN * CC, nullptr);

        // 3) gx = m @ w_ih[l]^T + b_ih[l]   (M=32768, N=384, K=128)
        sgemm_tile<0, 1><<<dim3(3, ROWS / 128, 1), 256>>>(
            p_m, w_ih + (long)l * 3 * CC * CC, p_gx,
            ROWS, 3 * CC, CC, CC, CC, 3 * CC, 0, 0, 0,
            b_ih + (long)l * 3 * CC);

        // 4) gh = h @ w_hh[l]^T + b_hh[l]
        sgemm_tile<0, 1><<<dim3(3, ROWS / 128, 1), 256>>>(
            hin, w_hh + (long)l * 3 * CC * CC, p_gh,
            ROWS, 3 * CC, CC, CC, CC, 3 * CC, 0, 0, 0,
            b_hh + (long)l * 3 * CC);

        // 5) GRU elementwise (mask applied on last layer)
        gru_elem<<<(ROWS * CC) / 256, 256>>>(
            p_gx, p_gh, hin, hout, mask, (l == LL - 1) ? 1 : 0);
    }
}

// round 3
// speedup vs baseline: 2.2825x; 2.2825x over previous
#include <cuda_runtime.h>
#include <cuda_bf16.h>
#include <cstdint>

// Problem constants: B=32, N=1024, C=128, L=4
#define BB 32
#define NN 1024
#define CC 128
#define LL 4
#define ROWS (BB * NN)          // 32768
#define HSZ  (ROWS * CC)
#define GSZ  (ROWS * 3 * CC)

// fp32 scratch
__device__ __align__(16) float g_h0[HSZ];
__device__ __align__(16) float g_h1[HSZ];
__device__ __align__(16) float g_hw[HSZ];
__device__ __align__(16) float g_m [HSZ];
__device__ __align__(16) float g_gx[GSZ];
__device__ __align__(16) float g_gh[GSZ];
// bf16 scratch
__device__ __align__(16) __nv_bfloat16 g_adjT[(size_t)BB * NN * NN];     // [b][n][j]
__device__ __align__(16) __nv_bfloat16 g_hwT_hi[(size_t)BB * CC * NN];   // [b][d][j]
__device__ __align__(16) __nv_bfloat16 g_hwT_lo[(size_t)BB * CC * NN];
__device__ __align__(16) __nv_bfloat16 g_hA_hi[HSZ];
__device__ __align__(16) __nv_bfloat16 g_hA_lo[HSZ];
__device__ __align__(16) __nv_bfloat16 g_mA_hi[HSZ];
__device__ __align__(16) __nv_bfloat16 g_mA_lo[HSZ];
__device__ __align__(16) __nv_bfloat16 g_wT_hi[LL * CC * CC];
__device__ __align__(16) __nv_bfloat16 g_wT_lo[LL * CC * CC];
__device__ __align__(16) __nv_bfloat16 g_wih_hi[LL * 3 * CC * CC];
__device__ __align__(16) __nv_bfloat16 g_wih_lo[LL * 3 * CC * CC];
__device__ __align__(16) __nv_bfloat16 g_whh_hi[LL * 3 * CC * CC];
__device__ __align__(16) __nv_bfloat16 g_whh_lo[LL * 3 * CC * CC];

// ===========================================================================
// helpers
// ===========================================================================
__device__ __forceinline__ uint32_t smem_u32(const void* p) {
    uint32_t a;
    asm("{ .reg .u64 t; cvta.to.shared.u64 t, %1; cvt.u32.u64 %0, t; }"
        : "=r"(a) : "l"(p));
    return a;
}
__device__ __forceinline__ void cp16(uint32_t s, const void* g) {
    asm volatile("cp.async.cg.shared.global [%0], [%1], 16;" :: "r"(s), "l"(g));
}
#define CP_COMMIT() asm volatile("cp.async.commit_group;" ::: "memory")
#define CP_WAIT(n)  asm volatile("cp.async.wait_group %0;" :: "n"(n) : "memory")

#define LDSM4(R0, R1, R2, R3, ADDR)                                          \
    asm volatile("ldmatrix.sync.aligned.m8n8.x4.shared.b16 {%0,%1,%2,%3}, [%4];" \
                 : "=r"(R0), "=r"(R1), "=r"(R2), "=r"(R3) : "r"(ADDR))

#define MMA16816(D, A, B0, B1)                                               \
    asm volatile(                                                            \
        "mma.sync.aligned.m16n8k16.row.col.f32.bf16.bf16.f32 "               \
        "{%0,%1,%2,%3},{%4,%5,%6,%7},{%8,%9},{%0,%1,%2,%3};"                 \
        : "+f"((D)[0]), "+f"((D)[1]), "+f"((D)[2]), "+f"((D)[3])             \
        : "r"((A)[0]), "r"((A)[1]), "r"((A)[2]), "r"((A)[3]),                \
          "r"(B0), "r"(B1))

#define STAGE 32768   // A tile 16KB + B tile 16KB
#define SMEM_DYN (2 * STAGE)

// Load a 128-row x 64-col bf16 tile (128B rows, XOR-swizzled) via cp.async.
__device__ __forceinline__ void cp_tile(const __nv_bfloat16* __restrict__ g,
                                        int Kelems, uint32_t sdst, int t, int kc)
{
    #pragma unroll
    for (int u = 0; u < 4; ++u) {
        const int unit = t + u * 256;          // 0..1023
        const int row  = unit >> 3;            // 0..127
        const int c16  = unit & 7;             // 16B col within 128B row
        const uint32_t sw = ((row << 7) + (c16 << 4)) ^ ((row & 7) << 4);
        cp16(sdst + sw, g + (size_t)row * Kelems + (kc << 6) + (c16 << 3));
    }
}

// ===========================================================================
// Unified warp-MMA GEMM:
//   C[m,n] = sum_{p<P} sum_k A_p[m,k] * B_p[n,k]  (+ bias[n])
// A_p: [Mtot, K] bf16 row-major (K contiguous); B_p: [Ntot, K] bf16 row-major.
// CTA tile 128x128, K chunk 64, double-buffered cp.async, 8 warps (32x64 each).
// ===========================================================================
template <int P>
__global__ __launch_bounds__(256)
void wmma_gemm(const __nv_bfloat16* __restrict__ a0, const __nv_bfloat16* __restrict__ a1,
               const __nv_bfloat16* __restrict__ a2,
               const __nv_bfloat16* __restrict__ b0, const __nv_bfloat16* __restrict__ b1,
               const __nv_bfloat16* __restrict__ b2,
               float* __restrict__ C, int K, int ldc,
               long sA, long sB, long sC,
               const float* __restrict__ bias)
{
    extern __shared__ __align__(128) char smem[];
    const uint32_t sbase = smem_u32(smem);

    const int t     = threadIdx.x;
    const int lane  = t & 31;
    const int warp  = t >> 5;
    const int mwarp = (warp >> 1) * 32;
    const int nwarp = (warp & 1) * 64;
    const int m0 = blockIdx.y * 128;
    const int n0 = blockIdx.x * 128;
    const int z  = blockIdx.z;

    const __nv_bfloat16* Ap[3] = {
        a0 + (size_t)z * sA + (size_t)m0 * K,
        a1 + (size_t)z * sA + (size_t)m0 * K,
        a2 + (size_t)z * sA + (size_t)m0 * K };
    const __nv_bfloat16* Bp[3] = {
        b0 + (size_t)z * sB + (size_t)n0 * K,
        b1 + (size_t)z * sB + (size_t)n0 * K,
        b2 + (size_t)z * sB + (size_t)n0 * K };
    C += (size_t)z * sC;

    const int K64 = K >> 6;
    const int NC  = P * K64;

    float acc[2][8][4];
    #pragma unroll
    for (int i = 0; i < 2; i++)
        #pragma unroll
        for (int j = 0; j < 8; j++)
            #pragma unroll
            for (int q = 0; q < 4; q++)
                acc[i][j][q] = 0.0f;

    // prefetch chunk 0
    cp_tile(Ap[0], K, sbase, t, 0);
    cp_tile(Bp[0], K, sbase + 16384, t, 0);
    CP_COMMIT();

    for (int c = 0; c < NC; ++c) {
        const int buf = c & 1;
        if (c + 1 < NC) {
            const int nc  = c + 1;
            const int np  = nc / K64;
            const int nkc = nc - np * K64;
            const uint32_t nb = sbase + (nc & 1) * STAGE;
            cp_tile(Ap[np], K, nb, t, nkc);
            cp_tile(Bp[np], K, nb + 16384, t, nkc);
            CP_COMMIT();
            CP_WAIT(1);
        } else {
            CP_WAIT(0);
        }
        __syncthreads();

        const uint32_t As = sbase + buf * STAGE;
        const uint32_t Bs = As + 16384;

        #pragma unroll
        for (int ks = 0; ks < 4; ++ks) {
            uint32_t a[2][4];
            #pragma unroll
            for (int mb = 0; mb < 2; ++mb) {
                const int row = mwarp + mb * 16 + (lane & 15);
                const int col = ks * 32 + ((lane >> 4) << 4);
                const uint32_t ad = As + (row << 7) + (col ^ ((row & 7) << 4));
                LDSM4(a[mb][0], a[mb][1], a[mb][2], a[mb][3], ad);
            }
            uint32_t b[4][4];
            #pragma unroll
            for (int nq = 0; nq < 4; ++nq) {
                const int row = nwarp + nq * 16 + ((lane >> 4) << 3) + (lane & 7);
                const int col = ks * 32 + (((lane >> 3) & 1) << 4);
                const uint32_t bd = Bs + (row << 7) + (col ^ ((row & 7) << 4));
                LDSM4(b[nq][0], b[nq][1], b[nq][2], b[nq][3], bd);
            }
            #pragma unroll
            for (int mb = 0; mb < 2; ++mb)
                #pragma unroll
                for (int n = 0; n < 8; ++n)
                    MMA16816(acc[mb][n], a[mb],
                             b[n >> 1][(n & 1) * 2], b[n >> 1][(n & 1) * 2 + 1]);
        }
        __syncthreads();
    }

    // epilogue
    const int rbase = m0 + mwarp + (lane >> 2);
    const int cbase = n0 + nwarp + (lane & 3) * 2;
    #pragma unroll
    for (int mb = 0; mb < 2; ++mb) {
        #pragma unroll
        for (int n = 0; n < 8; ++n) {
            const int gc = cbase + n * 8;
            float bx = 0.0f, by = 0.0f;
            if (bias) { bx = bias[gc]; by = bias[gc + 1]; }
            const int r = rbase + mb * 16;
            float2 v0 = { acc[mb][n][0] + bx, acc[mb][n][1] + by };
            float2 v1 = { acc[mb][n][2] + bx, acc[mb][n][3] + by };
            *reinterpret_cast<float2*>(&C[(size_t)r * ldc + gc])       = v0;
            *reinterpret_cast<float2*>(&C[(size_t)(r + 8) * ldc + gc]) = v1;
        }
    }
}

// ===========================================================================
// Prep kernels
// ===========================================================================
// adj fp32 [b][j][n] -> adjT bf16 [b][n][j]; binary => exact
__global__ __launch_bounds__(256)
void adj_transpose(const float* __restrict__ adj, __nv_bfloat16* __restrict__ adjT)
{
    __shared__ float tile[32][33];
    const int b  = blockIdx.z;
    const int j0 = blockIdx.x * 32;
    const int n0 = blockIdx.y * 32;
    const float* src = adj + (size_t)b * NN * NN;
    __nv_bfloat16* dst = adjT + (size_t)b * NN * NN;
    const int tx = threadIdx.x & 31, ty = threadIdx.x >> 5;
    #pragma unroll
    for (int r = ty; r < 32; r += 8)
        tile[r][tx] = src[(size_t)(j0 + r) * NN + n0 + tx];
    __syncthreads();
    #pragma unroll
    for (int r = ty; r < 32; r += 8)
        dst[(size_t)(n0 + r) * NN + j0 + tx] = __float2bfloat16(tile[tx][r]);
}

// hw fp32 [b][j][d] -> hwT hi/lo bf16 [b][d][j]
__global__ __launch_bounds__(256)
void hw_transpose_split(const float* __restrict__ hw,
                        __nv_bfloat16* __restrict__ hi_out,
                        __nv_bfloat16* __restrict__ lo_out)
{
    __shared__ float tile[32][33];
    const int b  = blockIdx.z;
    const int j0 = blockIdx.x * 32;
    const int d0 = blockIdx.y * 32;
    const float* src = hw + (size_t)b * NN * CC;
    const size_t obase = (size_t)b * CC * NN;
    const int tx = threadIdx.x & 31, ty = threadIdx.x >> 5;
    #pragma unroll
    for (int r = ty; r < 32; r += 8)
        tile[r][tx] = src[(size_t)(j0 + r) * CC + d0 + tx];
    __syncthreads();
    #pragma unroll
    for (int r = ty; r < 32; r += 8) {
        const float v = tile[tx][r];
        const __nv_bfloat16 h = __float2bfloat16(v);
        const float rem = v - __bfloat162float(h);
        hi_out[obase + (size_t)(d0 + r) * NN + j0 + tx] = h;
        lo_out[obase + (size_t)(d0 + r) * NN + j0 + tx] = __float2bfloat16(rem);
    }
}

// elementwise fp32 -> bf16 hi/lo
__global__ __launch_bounds__(256)
void split2(const float* __restrict__ x,
            __nv_bfloat16* __restrict__ hi, __nv_bfloat16* __restrict__ lo)
{
    const int i = blockIdx.x * blockDim.x + threadIdx.x;
    const float v = x[i];
    const __nv_bfloat16 h = __float2bfloat16(v);
    hi[i] = h;
    lo[i] = __float2bfloat16(v - __bfloat162float(h));
}

// weight[l] fp32 [C][C] (W[c][d]) -> WT hi/lo bf16 [l][d][c]
__global__ __launch_bounds__(256)
void wT_split(const float* __restrict__ W,
              __nv_bfloat16* __restrict__ hi, __nv_bfloat16* __restrict__ lo)
{
    __shared__ float tile[32][33];
    const int l  = blockIdx.z;
    const int c0 = blockIdx.x * 32;
    const int d0 = blockIdx.y * 32;
    const float* src = W + (size_t)l * CC * CC;
    const size_t ob = (size_t)l * CC * CC;
    const int tx = threadIdx.x & 31, ty = threadIdx.x >> 5;
    #pragma unroll
    for (int r = ty; r < 32; r += 8)
        tile[r][tx] = src[(size_t)(c0 + r) * CC + d0 + tx];
    __syncthreads();
    #pragma unroll
    for (int r = ty; r < 32; r += 8) {
        const float v = tile[tx][r];
        const __nv_bfloat16 h = __float2bfloat16(v);
        hi[ob + (size_t)(d0 + r) * CC + c0 + tx] = h;
        lo[ob + (size_t)(d0 + r) * CC + c0 + tx] = __float2bfloat16(v - __bfloat162float(h));
    }
}

// ===========================================================================
// Fused GRU elementwise
// ===========================================================================
__global__ __launch_bounds__(256)
void gru_elem(const float* __restrict__ gx, const float* __restrict__ gh,
              const float* __restrict__ h, float* __restrict__ hout,
              const float* __restrict__ mask, int applyMask)
{
    const int idx = blockIdx.x * blockDim.x + threadIdx.x;
    const int r = idx >> 7;
    const int c = idx & 127;

    const long gbase = (long)r * (3 * CC);
    const float xr = gx[gbase + c];
    const float xz = gx[gbase + CC + c];
    const float xn = gx[gbase + 2 * CC + c];
    const float hr = gh[gbase + c];
    const float hz = gh[gbase + CC + c];
    const float hn = gh[gbase + 2 * CC + c];

    const float rg = 1.0f / (1.0f + __expf(-(xr + hr)));
    const float zg = 1.0f / (1.0f + __expf(-(xz + hz)));
    const float ng = tanhf(xn + rg * hn);
    float hnew = (1.0f - zg) * ng + zg * h[idx];
    if (applyMask) hnew *= mask[r];
    hout[idx] = hnew;
}

// ===========================================================================
extern "C" void kernel_launch(void* const* d_in, const int* in_sizes, int n_in,
                              void* d_out, int out_size)
{
    const float* x      = (const float*)d_in[0];
    const float* adj    = (const float*)d_in[1];
    const float* mask   = (const float*)d_in[2];
    const float* weight = (const float*)d_in[3];
    const float* w_ih   = (const float*)d_in[4];
    const float* w_hh   = (const float*)d_in[5];
    const float* b_ih   = (const float*)d_in[6];
    const float* b_hh   = (const float*)d_in[7];
    float* out = (float*)d_out;

    float *p_h0, *p_h1, *p_hw, *p_m, *p_gx, *p_gh;
    __nv_bfloat16 *p_adjT, *p_hwhi, *p_hwlo, *p_hhi, *p_hlo, *p_mhi, *p_mlo;
    __nv_bfloat16 *p_wThi, *p_wTlo, *p_wihhi, *p_wihlo, *p_whhhi, *p_whhlo;
    cudaGetSymbolAddress((void**)&p_h0, g_h0);
    cudaGetSymbolAddress((void**)&p_h1, g_h1);
    cudaGetSymbolAddress((void**)&p_hw, g_hw);
    cudaGetSymbolAddress((void**)&p_m,  g_m);
    cudaGetSymbolAddress((void**)&p_gx, g_gx);
    cudaGetSymbolAddress((void**)&p_gh, g_gh);
    cudaGetSymbolAddress((void**)&p_adjT, g_adjT);
    cudaGetSymbolAddress((void**)&p_hwhi, g_hwT_hi);
    cudaGetSymbolAddress((void**)&p_hwlo, g_hwT_lo);
    cudaGetSymbolAddress((void**)&p_hhi, g_hA_hi);
    cudaGetSymbolAddress((void**)&p_hlo, g_hA_lo);
    cudaGetSymbolAddress((void**)&p_mhi, g_mA_hi);
    cudaGetSymbolAddress((void**)&p_mlo, g_mA_lo);
    cudaGetSymbolAddress((void**)&p_wThi, g_wT_hi);
    cudaGetSymbolAddress((void**)&p_wTlo, g_wT_lo);
    cudaGetSymbolAddress((void**)&p_wihhi, g_wih_hi);
    cudaGetSymbolAddress((void**)&p_wihlo, g_wih_lo);
    cudaGetSymbolAddress((void**)&p_whhhi, g_whh_hi);
    cudaGetSymbolAddress((void**)&p_whhlo, g_whh_lo);

    cudaFuncSetAttribute(wmma_gemm<2>, cudaFuncAttributeMaxDynamicSharedMemorySize, SMEM_DYN);
    cudaFuncSetAttribute(wmma_gemm<3>, cudaFuncAttributeMaxDynamicSharedMemorySize, SMEM_DYN);

    float* hbuf[2] = { p_h0, p_h1 };

    // ---- once per call ----
    adj_transpose<<<dim3(NN / 32, NN / 32, BB), 256>>>(adj, p_adjT);
    wT_split<<<dim3(CC / 32, CC / 32, LL), 256>>>(weight, p_wThi, p_wTlo);
    split2<<<(LL * 3 * CC * CC) / 256, 256>>>(w_ih, p_wihhi, p_wihlo);
    split2<<<(LL * 3 * CC * CC) / 256, 256>>>(w_hh, p_whhhi, p_whhlo);

    for (int l = 0; l < LL; l++) {
        const float* hin  = (l == 0) ? x : hbuf[(l + 1) & 1];
        float*       hout = (l == LL - 1) ? out : hbuf[l & 1];
        const long loffW  = (long)l * CC * CC;
        const long loffG  = (long)l * 3 * CC * CC;

        // 0) split h -> bf16 hi/lo
        split2<<<HSZ / 256, 256>>>(hin, p_hhi, p_hlo);

        // 1) hw = h @ W[l]    (3 products: hihi + hilo + lohi)
        wmma_gemm<3><<<dim3(1, ROWS / 128, 1), 256, SMEM_DYN>>>(
            p_hhi, p_hhi, p_hlo,
            p_wThi + loffW, p_wTlo + loffW, p_wThi + loffW,
            p_hw, CC, CC, 0, 0, 0, nullptr);

        // 2a) hw -> hwT hi/lo [b][d][j]
        hw_transpose_split<<<dim3(NN / 32, CC / 32, BB), 256>>>(p_hw, p_hwhi, p_hwlo);

        // 2b) m[b] = adjT[b] @ hwT[b]^T  (2 products: A exact x {hi,lo})
        wmma_gemm<2><<<dim3(1, NN / 128, BB), 256, SMEM_DYN>>>(
            p_adjT, p_adjT, p_adjT,
            p_hwhi, p_hwlo, p_hwhi,
            p_m, NN, CC,
            (long)NN * NN, (long)CC * NN, (long)NN * CC, nullptr);

        // 2c) split m
        split2<<<HSZ / 256, 256>>>(p_m, p_mhi, p_mlo);

        // 3) gx = m @ w_ih[l]^T + b_ih[l]
        wmma_gemm<3><<<dim3(3, ROWS / 128, 1), 256, SMEM_DYN>>>(
            p_mhi, p_mhi, p_mlo,
            p_wihhi + loffG, p_wihlo + loffG, p_wihhi + loffG,
            p_gx, CC, 3 * CC, 0, 0, 0, b_ih + (long)l * 3 * CC);

        // 4) gh = h @ w_hh[l]^T + b_hh[l]
        wmma_gemm<3><<<dim3(3, ROWS / 128, 1), 256, SMEM_DYN>>>(
            p_hhi, p_hhi, p_hlo,
            p_whhhi + loffG, p_whhlo + loffG, p_whhhi + loffG,
            p_gh, CC, 3 * CC, 0, 0, 0, b_hh + (long)l * 3 * CC);

        // 5) GRU elementwise
        gru_elem<<<(ROWS * CC) / 256, 256>>>(
            p_gx, p_gh, hin, hout, mask, (l == LL - 1) ? 1 : 0);
    }
}

// round 4
// speedup vs baseline: 2.4264x; 1.0630x over previous
#include <cuda_runtime.h>
#include <cuda_bf16.h>
#include <cstdint>

// Problem constants: B=32, N=1024, C=128, L=4
#define BB 32
#define NN 1024
#define CC 128
#define LL 4
#define ROWS (BB * NN)          // 32768
#define HSZ  (ROWS * CC)
#define GSZ  (ROWS * 3 * CC)

// fp32 scratch
__device__ __align__(16) float g_h0[HSZ];
__device__ __align__(16) float g_h1[HSZ];
__device__ __align__(16) float g_gx[GSZ];
__device__ __align__(16) float g_gh[GSZ];
// bf16 scratch
__device__ __align__(16) __nv_bfloat16 g_adjT[(size_t)BB * NN * NN];   // [b][n][j]
__device__ __align__(16) __nv_bfloat16 g_hwT_hi[HSZ];                  // [d][b*N+j]
__device__ __align__(16) __nv_bfloat16 g_hwT_lo[HSZ];
__device__ __align__(16) __nv_bfloat16 g_hA_hi[HSZ];                   // h  [row][c]
__device__ __align__(16) __nv_bfloat16 g_hA_lo[HSZ];
__device__ __align__(16) __nv_bfloat16 g_mA_hi[HSZ];                   // m  [row][c]
__device__ __align__(16) __nv_bfloat16 g_mA_lo[HSZ];
__device__ __align__(16) __nv_bfloat16 g_wT_hi[LL * CC * CC];          // [l][d][c]
__device__ __align__(16) __nv_bfloat16 g_wT_lo[LL * CC * CC];
__device__ __align__(16) __nv_bfloat16 g_wih_hi[LL * 3 * CC * CC];
__device__ __align__(16) __nv_bfloat16 g_wih_lo[LL * 3 * CC * CC];
__device__ __align__(16) __nv_bfloat16 g_whh_hi[LL * 3 * CC * CC];
__device__ __align__(16) __nv_bfloat16 g_whh_lo[LL * 3 * CC * CC];

// ===========================================================================
// helpers
// ===========================================================================
__device__ __forceinline__ uint32_t smem_u32(const void* p) {
    uint32_t a;
    asm("{ .reg .u64 t; cvta.to.shared.u64 t, %1; cvt.u32.u64 %0, t; }"
        : "=r"(a) : "l"(p));
    return a;
}
__device__ __forceinline__ void cp16(uint32_t s, const void* g) {
    asm volatile("cp.async.cg.shared.global [%0], [%1], 16;" :: "r"(s), "l"(g));
}
#define CP_COMMIT() asm volatile("cp.async.commit_group;" ::: "memory")
#define CP_WAIT(n)  asm volatile("cp.async.wait_group %0;" :: "n"(n) : "memory")

#define LDSM4(R0, R1, R2, R3, ADDR)                                          \
    asm volatile("ldmatrix.sync.aligned.m8n8.x4.shared.b16 {%0,%1,%2,%3}, [%4];" \
                 : "=r"(R0), "=r"(R1), "=r"(R2), "=r"(R3) : "r"(ADDR))

#define MMA16816(D, A, B0, B1)                                               \
    asm volatile(                                                            \
        "mma.sync.aligned.m16n8k16.row.col.f32.bf16.bf16.f32 "               \
        "{%0,%1,%2,%3},{%4,%5,%6,%7},{%8,%9},{%0,%1,%2,%3};"                 \
        : "+f"((D)[0]), "+f"((D)[1]), "+f"((D)[2]), "+f"((D)[3])             \
        : "r"((A)[0]), "r"((A)[1]), "r"((A)[2]), "r"((A)[3]),                \
          "r"(B0), "r"(B1))

// Load a 128-row x 64-col bf16 tile (128B rows, XOR-16B swizzle) via cp.async.
__device__ __forceinline__ void cp_tile(const __nv_bfloat16* __restrict__ g,
                                        int stride, uint32_t sdst, int t, int kc)
{
    #pragma unroll
    for (int u = 0; u < 4; ++u) {
        const int unit = t + u * 256;          // 0..1023
        const int row  = unit >> 3;            // 0..127
        const int c16  = unit & 7;             // 16B col within 128B row
        const uint32_t sw = ((row << 7) + (c16 << 4)) ^ ((row & 7) << 4);
        cp16(sdst + sw, g + (size_t)row * stride + (kc << 6) + (c16 << 3));
    }
}

// ===========================================================================
// Fused multi-product warp-MMA GEMM.
//  MODE 0 (ADJ):    C = A @ (Bhi + Blo)^T          (A exact bf16)
//  MODE 1 (SPLIT3): C = Ahi@Bhi^T + Ahi@Blo^T + Alo@Bhi^T
//  OUTF 0: fp32 C (+bias);  OUTF 1: bf16 hi/lo C (epilogue split)
// A rows: [M][K] (stride lda); B rows: [N][K] (stride ldb). CTA tile 128x128.
// K chunk 64, double-buffered cp.async, 8 warps (32x64 warp tiles).
// ===========================================================================
template <int MODE, int OUTF>
__global__ __launch_bounds__(256)
void wmma2(const __nv_bfloat16* __restrict__ a_hi, const __nv_bfloat16* __restrict__ a_lo,
           const __nv_bfloat16* __restrict__ b_hi, const __nv_bfloat16* __restrict__ b_lo,
           float* __restrict__ Cf,
           __nv_bfloat16* __restrict__ Chi, __nv_bfloat16* __restrict__ Clo,
           int K, int lda, int ldb, int ldc,
           long sA, long sB, long sC, const float* __restrict__ bias)
{
    constexpr int NT = (MODE == 0) ? 3 : 4;           // tiles per stage
    constexpr uint32_t TSZ = 16384;
    constexpr uint32_t STG = NT * TSZ;
    extern __shared__ __align__(128) char smem[];
    const uint32_t sbase = smem_u32(smem);

    const int t     = threadIdx.x;
    const int lane  = t & 31;
    const int warp  = t >> 5;
    const int mwarp = (warp >> 1) * 32;
    const int nwarp = (warp & 1) * 64;
    const int m0 = blockIdx.y * 128;
    const int n0 = blockIdx.x * 128;
    const int z  = blockIdx.z;

    const __nv_bfloat16* Ah = a_hi + (size_t)z * sA + (size_t)m0 * lda;
    const __nv_bfloat16* Al = (MODE == 1) ? a_lo + (size_t)z * sA + (size_t)m0 * lda : Ah;
    const __nv_bfloat16* Bh = b_hi + (size_t)z * sB + (size_t)n0 * ldb;
    const __nv_bfloat16* Bl = b_lo + (size_t)z * sB + (size_t)n0 * ldb;

    const int NC = K >> 6;

    float acc[2][8][4];
    #pragma unroll
    for (int i = 0; i < 2; i++)
        #pragma unroll
        for (int j = 0; j < 8; j++)
            #pragma unroll
            for (int q = 0; q < 4; q++)
                acc[i][j][q] = 0.0f;

    // stage loader
    auto load_stage = [&](int kc, uint32_t sb) {
        if (MODE == 0) {
            cp_tile(Ah, lda, sb, t, kc);
            cp_tile(Bh, ldb, sb + TSZ, t, kc);
            cp_tile(Bl, ldb, sb + 2 * TSZ, t, kc);
        } else {
            cp_tile(Ah, lda, sb, t, kc);
            cp_tile(Al, lda, sb + TSZ, t, kc);
            cp_tile(Bh, ldb, sb + 2 * TSZ, t, kc);
            cp_tile(Bl, ldb, sb + 3 * TSZ, t, kc);
        }
        CP_COMMIT();
    };

    load_stage(0, sbase);

    for (int c = 0; c < NC; ++c) {
        const int buf = c & 1;
        if (c + 1 < NC) {
            load_stage(c + 1, sbase + ((c + 1) & 1) * STG);
            CP_WAIT(1);
        } else {
            CP_WAIT(0);
        }
        __syncthreads();

        const uint32_t S = sbase + buf * STG;

        #pragma unroll
        for (int ks = 0; ks < 4; ++ks) {
            // ---- A fragments ----
            uint32_t ah[2][4], al[2][4];
            #pragma unroll
            for (int mb = 0; mb < 2; ++mb) {
                const int row = mwarp + mb * 16 + (lane & 15);
                const int col = ks * 32 + ((lane >> 4) << 4);
                const uint32_t sw = (row << 7) + (col ^ ((row & 7) << 4));
                LDSM4(ah[mb][0], ah[mb][1], ah[mb][2], ah[mb][3], S + sw);
                if (MODE == 1)
                    LDSM4(al[mb][0], al[mb][1], al[mb][2], al[mb][3], S + TSZ + sw);
            }
            // ---- B fragments ----
            const uint32_t Bbase = S + (MODE == 0 ? TSZ : 2 * TSZ);
            uint32_t bh[4][4], bl[4][4];
            #pragma unroll
            for (int nq = 0; nq < 4; ++nq) {
                const int row = nwarp + nq * 16 + ((lane >> 4) << 3) + (lane & 7);
                const int col = ks * 32 + (((lane >> 3) & 1) << 4);
                const uint32_t sw = (row << 7) + (col ^ ((row & 7) << 4));
                LDSM4(bh[nq][0], bh[nq][1], bh[nq][2], bh[nq][3], Bbase + sw);
                LDSM4(bl[nq][0], bl[nq][1], bl[nq][2], bl[nq][3], Bbase + TSZ + sw);
            }
            // ---- MMAs ----
            #pragma unroll
            for (int mb = 0; mb < 2; ++mb)
                #pragma unroll
                for (int n = 0; n < 8; ++n) {
                    const int q0 = (n & 1) * 2;
                    MMA16816(acc[mb][n], ah[mb], bh[n >> 1][q0], bh[n >> 1][q0 + 1]);
                    MMA16816(acc[mb][n], ah[mb], bl[n >> 1][q0], bl[n >> 1][q0 + 1]);
                    if (MODE == 1)
                        MMA16816(acc[mb][n], al[mb], bh[n >> 1][q0], bh[n >> 1][q0 + 1]);
                }
        }
        __syncthreads();
    }

    // ---- epilogue ----
    const int rbase = m0 + mwarp + (lane >> 2);
    const int cbase = n0 + nwarp + (lane & 3) * 2;

    if (OUTF == 0) {
        float* C = Cf + (size_t)z * sC;
        #pragma unroll
        for (int mb = 0; mb < 2; ++mb) {
            #pragma unroll
            for (int n = 0; n < 8; ++n) {
                const int gc = cbase + n * 8;
                float bx = 0.0f, by = 0.0f;
                if (bias) { bx = bias[gc]; by = bias[gc + 1]; }
                const int r = rbase + mb * 16;
                float2 v0 = { acc[mb][n][0] + bx, acc[mb][n][1] + by };
                float2 v1 = { acc[mb][n][2] + bx, acc[mb][n][3] + by };
                *reinterpret_cast<float2*>(&C[(size_t)r * ldc + gc])       = v0;
                *reinterpret_cast<float2*>(&C[(size_t)(r + 8) * ldc + gc]) = v1;
            }
        }
    } else {
        __nv_bfloat16* CH = Chi + (size_t)z * sC;
        __nv_bfloat16* CL = Clo + (size_t)z * sC;
        #pragma unroll
        for (int mb = 0; mb < 2; ++mb) {
            #pragma unroll
            for (int n = 0; n < 8; ++n) {
                const int gc = cbase + n * 8;
                const int r  = rbase + mb * 16;
                #pragma unroll
                for (int half = 0; half < 2; ++half) {
                    const float v0 = acc[mb][n][half * 2 + 0];
                    const float v1 = acc[mb][n][half * 2 + 1];
                    const __nv_bfloat16 h0 = __float2bfloat16(v0);
                    const __nv_bfloat16 h1 = __float2bfloat16(v1);
                    __nv_bfloat162 ph; ph.x = h0; ph.y = h1;
                    __nv_bfloat162 pl;
                    pl.x = __float2bfloat16(v0 - __bfloat162float(h0));
                    pl.y = __float2bfloat16(v1 - __bfloat162float(h1));
                    const size_t off = (size_t)(r + half * 8) * ldc + gc;
                    *reinterpret_cast<__nv_bfloat162*>(&CH[off]) = ph;
                    *reinterpret_cast<__nv_bfloat162*>(&CL[off]) = pl;
                }
            }
        }
    }
}

// ===========================================================================
// Prep kernels
// ===========================================================================
__global__ __launch_bounds__(256)
void adj_transpose(const float* __restrict__ adj, __nv_bfloat16* __restrict__ adjT)
{
    __shared__ float tile[32][33];
    const int b  = blockIdx.z;
    const int j0 = blockIdx.x * 32;
    const int n0 = blockIdx.y * 32;
    const float* src = adj + (size_t)b * NN * NN;
    __nv_bfloat16* dst = adjT + (size_t)b * NN * NN;
    const int tx = threadIdx.x & 31, ty = threadIdx.x >> 5;
    #pragma unroll
    for (int r = ty; r < 32; r += 8)
        tile[r][tx] = src[(size_t)(j0 + r) * NN + n0 + tx];
    __syncthreads();
    #pragma unroll
    for (int r = ty; r < 32; r += 8)
        dst[(size_t)(n0 + r) * NN + j0 + tx] = __float2bfloat16(tile[tx][r]);
}

__global__ __launch_bounds__(256)
void split2(const float* __restrict__ x,
            __nv_bfloat16* __restrict__ hi, __nv_bfloat16* __restrict__ lo)
{
    const int i = blockIdx.x * blockDim.x + threadIdx.x;
    const float v = x[i];
    const __nv_bfloat16 h = __float2bfloat16(v);
    hi[i] = h;
    lo[i] = __float2bfloat16(v - __bfloat162float(h));
}

// weight[l] fp32 [C][C] (W[c][d]) -> WT hi/lo bf16 [l][d][c]
__global__ __launch_bounds__(256)
void wT_split(const float* __restrict__ W,
              __nv_bfloat16* __restrict__ hi, __nv_bfloat16* __restrict__ lo)
{
    __shared__ float tile[32][33];
    const int l  = blockIdx.z;
    const int c0 = blockIdx.x * 32;
    const int d0 = blockIdx.y * 32;
    const float* src = W + (size_t)l * CC * CC;
    const size_t ob = (size_t)l * CC * CC;
    const int tx = threadIdx.x & 31, ty = threadIdx.x >> 5;
    #pragma unroll
    for (int r = ty; r < 32; r += 8)
        tile[r][tx] = src[(size_t)(c0 + r) * CC + d0 + tx];
    __syncthreads();
    #pragma unroll
    for (int r = ty; r < 32; r += 8) {
        const float v = tile[tx][r];
        const __nv_bfloat16 h = __float2bfloat16(v);
        hi[ob + (size_t)(d0 + r) * CC + c0 + tx] = h;
        lo[ob + (size_t)(d0 + r) * CC + c0 + tx] = __float2bfloat16(v - __bfloat162float(h));
    }
}

// ===========================================================================
// Fused GRU elementwise (+ optional bf16 hi/lo output for next layer)
// ===========================================================================
__global__ __launch_bounds__(256)
void gru_elem2(const float* __restrict__ gx, const float* __restrict__ gh,
               const float* __restrict__ h, float* __restrict__ hout,
               __nv_bfloat16* __restrict__ hhi, __nv_bfloat16* __restrict__ hlo,
               const float* __restrict__ mask, int applyMask, int writeSplit)
{
    const int idx = blockIdx.x * blockDim.x + threadIdx.x;
    const int r = idx >> 7;
    const int c = idx & 127;

    const long gbase = (long)r * (3 * CC);
    const float xr = gx[gbase + c];
    const float xz = gx[gbase + CC + c];
    const float xn = gx[gbase + 2 * CC + c];
    const float hr = gh[gbase + c];
    const float hz = gh[gbase + CC + c];
    const float hn = gh[gbase + 2 * CC + c];

    const float rg = 1.0f / (1.0f + __expf(-(xr + hr)));
    const float zg = 1.0f / (1.0f + __expf(-(xz + hz)));
    const float ng = tanhf(xn + rg * hn);
    float hnew = (1.0f - zg) * ng + zg * h[idx];
    hout[idx] = applyMask ? hnew * mask[r] : hnew;
    if (writeSplit) {
        const __nv_bfloat16 hb = __float2bfloat16(hnew);
        hhi[idx] = hb;
        hlo[idx] = __float2bfloat16(hnew - __bfloat162float(hb));
    }
}

// ===========================================================================
#define SMEM_ADJ    (2 * 3 * 16384)   // 96 KB
#define SMEM_SPLIT3 (2 * 4 * 16384)   // 128 KB

extern "C" void kernel_launch(void* const* d_in, const int* in_sizes, int n_in,
                              void* d_out, int out_size)
{
    const float* x      = (const float*)d_in[0];
    const float* adj    = (const float*)d_in[1];
    const float* mask   = (const float*)d_in[2];
    const float* weight = (const float*)d_in[3];
    const float* w_ih   = (const float*)d_in[4];
    const float* w_hh   = (const float*)d_in[5];
    const float* b_ih   = (const float*)d_in[6];
    const float* b_hh   = (const float*)d_in[7];
    float* out = (float*)d_out;

    float *p_h0, *p_h1, *p_gx, *p_gh;
    __nv_bfloat16 *p_adjT, *p_hwhi, *p_hwlo, *p_hhi, *p_hlo, *p_mhi, *p_mlo;
    __nv_bfloat16 *p_wThi, *p_wTlo, *p_wihhi, *p_wihlo, *p_whhhi, *p_whhlo;
    cudaGetSymbolAddress((void**)&p_h0, g_h0);
    cudaGetSymbolAddress((void**)&p_h1, g_h1);
    cudaGetSymbolAddress((void**)&p_gx, g_gx);
    cudaGetSymbolAddress((void**)&p_gh, g_gh);
    cudaGetSymbolAddress((void**)&p_adjT, g_adjT);
    cudaGetSymbolAddress((void**)&p_hwhi, g_hwT_hi);
    cudaGetSymbolAddress((void**)&p_hwlo, g_hwT_lo);
    cudaGetSymbolAddress((void**)&p_hhi, g_hA_hi);
    cudaGetSymbolAddress((void**)&p_hlo, g_hA_lo);
    cudaGetSymbolAddress((void**)&p_mhi, g_mA_hi);
    cudaGetSymbolAddress((void**)&p_mlo, g_mA_lo);
    cudaGetSymbolAddress((void**)&p_wThi, g_wT_hi);
    cudaGetSymbolAddress((void**)&p_wTlo, g_wT_lo);
    cudaGetSymbolAddress((void**)&p_wihhi, g_wih_hi);
    cudaGetSymbolAddress((void**)&p_wihlo, g_wih_lo);
    cudaGetSymbolAddress((void**)&p_whhhi, g_whh_hi);
    cudaGetSymbolAddress((void**)&p_whhlo, g_whh_lo);

    cudaFuncSetAttribute(wmma2<0, 1>, cudaFuncAttributeMaxDynamicSharedMemorySize, SMEM_ADJ);
    cudaFuncSetAttribute(wmma2<1, 1>, cudaFuncAttributeMaxDynamicSharedMemorySize, SMEM_SPLIT3);
    cudaFuncSetAttribute(wmma2<1, 0>, cudaFuncAttributeMaxDynamicSharedMemorySize, SMEM_SPLIT3);

    float* hbuf[2] = { p_h0, p_h1 };

    // ---- once per call ----
    adj_transpose<<<dim3(NN / 32, NN / 32, BB), 256>>>(adj, p_adjT);
    wT_split<<<dim3(CC / 32, CC / 32, LL), 256>>>(weight, p_wThi, p_wTlo);
    split2<<<(LL * 3 * CC * CC) / 256, 256>>>(w_ih, p_wihhi, p_wihlo);
    split2<<<(LL * 3 * CC * CC) / 256, 256>>>(w_hh, p_whhhi, p_whhlo);
    split2<<<HSZ / 256, 256>>>(x, p_hhi, p_hlo);     // h0 = x

    for (int l = 0; l < LL; l++) {
        const float* hin  = (l == 0) ? x : hbuf[(l + 1) & 1];
        float*       hout = (l == LL - 1) ? out : hbuf[l & 1];
        const long loffW  = (long)l * CC * CC;
        const long loffG  = (long)l * 3 * CC * CC;

        // 1) hwT[d][b*N+j] = sum_c WT[d][c] * h[j][c]  -> bf16 hi/lo
        //    (M=128 rows d, N=32768 cols j, K=128)
        wmma2<1, 1><<<dim3(ROWS / 128, 1, 1), 256, SMEM_SPLIT3>>>(
            p_wThi + loffW, p_wTlo + loffW, p_hhi, p_hlo,
            nullptr, p_hwhi, p_hwlo,
            CC, CC, CC, ROWS, 0, 0, 0, nullptr);

        // 2) m[b][n][d] = sum_j adjT[b][n][j] * (hwT_hi+hwT_lo)[d][b*N+j] -> bf16 hi/lo
        wmma2<0, 1><<<dim3(1, NN / 128, BB), 256, SMEM_ADJ>>>(
            p_adjT, p_adjT, p_hwhi, p_hwlo,
            nullptr, p_mhi, p_mlo,
            NN, NN, ROWS, CC,
            (long)NN * NN, (long)NN, (long)NN * CC, nullptr);

        // 3) gx = m @ w_ih^T + b_ih   (fp32)
        wmma2<1, 0><<<dim3(3, ROWS / 128, 1), 256, SMEM_SPLIT3>>>(
            p_mhi, p_mlo, p_wihhi + loffG, p_wihlo + loffG,
            p_gx, nullptr, nullptr,
            CC, CC, CC, 3 * CC, 0, 0, 0, b_ih + (long)l * 3 * CC);

        // 4) gh = h @ w_hh^T + b_hh   (fp32)
        wmma2<1, 0><<<dim3(3, ROWS / 128, 1), 256, SMEM_SPLIT3>>>(
            p_hhi, p_hlo, p_whhhi + loffG, p_whhlo + loffG,
            p_gh, nullptr, nullptr,
            CC, CC, CC, 3 * CC, 0, 0, 0, b_hh + (long)l * 3 * CC);

        // 5) GRU elementwise (+ split h for next layer)
        gru_elem2<<<(ROWS * CC) / 256, 256>>>(
            p_gx, p_gh, hin, hout, p_hhi, p_hlo, mask,
            (l == LL - 1) ? 1 : 0, (l == LL - 1) ? 0 : 1);
    }
}

// round 5
// speedup vs baseline: 2.5620x; 1.0559x over previous
#include <cuda_runtime.h>
#include <cuda_bf16.h>
#include <cstdint>

// Problem constants: B=32, N=1024, C=128, L=4
#define BB 32
#define NN 1024
#define CC 128
#define LL 4
#define ROWS (BB * NN)          // 32768
#define HSZ  (ROWS * CC)
#define GSZ  (ROWS * 3 * CC)

// fp32 scratch
__device__ __align__(16) float g_h0[HSZ];
__device__ __align__(16) float g_h1[HSZ];
__device__ __align__(16) float g_gx[GSZ];
__device__ __align__(16) float g_gh[GSZ];
// bf16 scratch
__device__ __align__(16) __nv_bfloat16 g_adjT[(size_t)BB * NN * NN];   // [b][n][j]
__device__ __align__(16) __nv_bfloat16 g_hwT_hi[HSZ];                  // [d][b*N+j]
__device__ __align__(16) __nv_bfloat16 g_hwT_lo[HSZ];
__device__ __align__(16) __nv_bfloat16 g_hA_hi[HSZ];                   // h  [row][c]
__device__ __align__(16) __nv_bfloat16 g_hA_lo[HSZ];
__device__ __align__(16) __nv_bfloat16 g_mA_hi[HSZ];                   // m  [row][c]
__device__ __align__(16) __nv_bfloat16 g_mA_lo[HSZ];
__device__ __align__(16) __nv_bfloat16 g_wT_hi[LL * CC * CC];          // [l][d][c]
__device__ __align__(16) __nv_bfloat16 g_wT_lo[LL * CC * CC];
__device__ __align__(16) __nv_bfloat16 g_wih_hi[LL * 3 * CC * CC];
__device__ __align__(16) __nv_bfloat16 g_wih_lo[LL * 3 * CC * CC];
__device__ __align__(16) __nv_bfloat16 g_whh_hi[LL * 3 * CC * CC];
__device__ __align__(16) __nv_bfloat16 g_whh_lo[LL * 3 * CC * CC];

// ===========================================================================
// helpers
// ===========================================================================
__device__ __forceinline__ uint32_t smem_u32(const void* p) {
    uint32_t a;
    asm("{ .reg .u64 t; cvta.to.shared.u64 t, %1; cvt.u32.u64 %0, t; }"
        : "=r"(a) : "l"(p));
    return a;
}
__device__ __forceinline__ void cp16(uint32_t s, const void* g) {
    asm volatile("cp.async.cg.shared.global [%0], [%1], 16;" :: "r"(s), "l"(g));
}
#define CP_COMMIT() asm volatile("cp.async.commit_group;" ::: "memory")
#define CP_WAIT(n)  asm volatile("cp.async.wait_group %0;" :: "n"(n) : "memory")

#define LDSM4(R0, R1, R2, R3, ADDR)                                          \
    asm volatile("ldmatrix.sync.aligned.m8n8.x4.shared.b16 {%0,%1,%2,%3}, [%4];" \
                 : "=r"(R0), "=r"(R1), "=r"(R2), "=r"(R3) : "r"(ADDR))

#define MMA16816(D, A, B0, B1)                                               \
    asm volatile(                                                            \
        "mma.sync.aligned.m16n8k16.row.col.f32.bf16.bf16.f32 "               \
        "{%0,%1,%2,%3},{%4,%5,%6,%7},{%8,%9},{%0,%1,%2,%3};"                 \
        : "+f"((D)[0]), "+f"((D)[1]), "+f"((D)[2]), "+f"((D)[3])             \
        : "r"((A)[0]), "r"((A)[1]), "r"((A)[2]), "r"((A)[3]),                \
          "r"(B0), "r"(B1))

// Load an R-row x 64-col bf16 tile (128B rows, XOR-16B swizzle) via cp.async.
template <int R>
__device__ __forceinline__ void cp_tile(const __nv_bfloat16* __restrict__ g,
                                        int stride, uint32_t sdst, int t, int kc)
{
    #pragma unroll
    for (int u = 0; u < R / 32; ++u) {
        const int unit = t + u * 256;
        const int row  = unit >> 3;
        const int c16  = unit & 7;
        const uint32_t sw = ((row << 7) + (c16 << 4)) ^ ((row & 7) << 4);
        cp16(sdst + sw, g + (size_t)row * stride + (kc << 6) + (c16 << 3));
    }
}

// ===========================================================================
// wmma3: CTA tile 256x128, warp tile 64x64 (8 warps: 4 m x 2 n).
//  MODE 0 (ADJ):    C = A @ (Bhi + Blo)^T          (A exact bf16)
//  MODE 1 (SPLIT3): C = Ahi@Bhi^T + Ahi@Blo^T + Alo@Bhi^T
//  OUTF 0: fp32 C (+bias);  OUTF 1: bf16 hi/lo C (epilogue split)
// A rows: [M][K] stride lda; B rows: [N][K] stride ldb. K chunk 64, 2 stages.
// ===========================================================================
template <int MODE, int OUTF>
__global__ __launch_bounds__(256)
void wmma3(const __nv_bfloat16* __restrict__ a_hi, const __nv_bfloat16* __restrict__ a_lo,
           const __nv_bfloat16* __restrict__ b_hi, const __nv_bfloat16* __restrict__ b_lo,
           float* __restrict__ Cf,
           __nv_bfloat16* __restrict__ Chi, __nv_bfloat16* __restrict__ Clo,
           int K, int lda, int ldb, int ldc,
           long sA, long sB, long sC, const float* __restrict__ bias)
{
    constexpr uint32_t ATSZ = 32768;   // 256 x 64 x 2B
    constexpr uint32_t BTSZ = 16384;   // 128 x 64 x 2B
    constexpr uint32_t STG  = (MODE == 0) ? (ATSZ + 2 * BTSZ)            // 64KB
                                          : (2 * ATSZ + 2 * BTSZ);       // 96KB
    extern __shared__ __align__(128) char smem[];
    const uint32_t sbase = smem_u32(smem);

    const int t     = threadIdx.x;
    const int lane  = t & 31;
    const int warp  = t >> 5;
    const int mwarp = (warp >> 1) * 64;
    const int nwarp = (warp & 1) * 64;
    const int m0 = blockIdx.y * 256;
    const int n0 = blockIdx.x * 128;
    const int z  = blockIdx.z;

    const __nv_bfloat16* Ah = a_hi + (size_t)z * sA + (size_t)m0 * lda;
    const __nv_bfloat16* Al = (MODE == 1) ? a_lo + (size_t)z * sA + (size_t)m0 * lda : Ah;
    const __nv_bfloat16* Bh = b_hi + (size_t)z * sB + (size_t)n0 * ldb;
    const __nv_bfloat16* Bl = b_lo + (size_t)z * sB + (size_t)n0 * ldb;

    const int NC = K >> 6;

    float acc[4][8][4];
    #pragma unroll
    for (int i = 0; i < 4; i++)
        #pragma unroll
        for (int j = 0; j < 8; j++)
            #pragma unroll
            for (int q = 0; q < 4; q++)
                acc[i][j][q] = 0.0f;

    auto load_stage = [&](int kc, uint32_t sb) {
        if (MODE == 0) {
            cp_tile<256>(Ah, lda, sb, t, kc);
            cp_tile<128>(Bh, ldb, sb + ATSZ, t, kc);
            cp_tile<128>(Bl, ldb, sb + ATSZ + BTSZ, t, kc);
        } else {
            cp_tile<256>(Ah, lda, sb, t, kc);
            cp_tile<256>(Al, lda, sb + ATSZ, t, kc);
            cp_tile<128>(Bh, ldb, sb + 2 * ATSZ, t, kc);
            cp_tile<128>(Bl, ldb, sb + 2 * ATSZ + BTSZ, t, kc);
        }
        CP_COMMIT();
    };

    load_stage(0, sbase);

    for (int c = 0; c < NC; ++c) {
        const int buf = c & 1;
        if (c + 1 < NC) {
            load_stage(c + 1, sbase + ((c + 1) & 1) * STG);
            CP_WAIT(1);
        } else {
            CP_WAIT(0);
        }
        __syncthreads();

        const uint32_t S = sbase + buf * STG;
        const uint32_t BbaseS = S + (MODE == 0 ? ATSZ : 2 * ATSZ);

        #pragma unroll
        for (int ks = 0; ks < 4; ++ks) {
            // ---- A fragments (4 m-blocks of 16) ----
            uint32_t ah[4][4], al[4][4];
            #pragma unroll
            for (int mb = 0; mb < 4; ++mb) {
                const int row = mwarp + mb * 16 + (lane & 15);
                const int col = ks * 32 + ((lane >> 4) << 4);
                const uint32_t sw = (row << 7) + (col ^ ((row & 7) << 4));
                LDSM4(ah[mb][0], ah[mb][1], ah[mb][2], ah[mb][3], S + sw);
                if (MODE == 1)
                    LDSM4(al[mb][0], al[mb][1], al[mb][2], al[mb][3], S + ATSZ + sw);
            }
            // ---- B fragments ----
            uint32_t bh[4][4], bl[4][4];
            #pragma unroll
            for (int nq = 0; nq < 4; ++nq) {
                const int row = nwarp + nq * 16 + ((lane >> 4) << 3) + (lane & 7);
                const int col = ks * 32 + (((lane >> 3) & 1) << 4);
                const uint32_t sw = (row << 7) + (col ^ ((row & 7) << 4));
                LDSM4(bh[nq][0], bh[nq][1], bh[nq][2], bh[nq][3], BbaseS + sw);
                LDSM4(bl[nq][0], bl[nq][1], bl[nq][2], bl[nq][3], BbaseS + BTSZ + sw);
            }
            // ---- MMAs ----
            #pragma unroll
            for (int mb = 0; mb < 4; ++mb)
                #pragma unroll
                for (int n = 0; n < 8; ++n) {
                    const int q0 = (n & 1) * 2;
                    MMA16816(acc[mb][n], ah[mb], bh[n >> 1][q0], bh[n >> 1][q0 + 1]);
                    MMA16816(acc[mb][n], ah[mb], bl[n >> 1][q0], bl[n >> 1][q0 + 1]);
                    if (MODE == 1)
                        MMA16816(acc[mb][n], al[mb], bh[n >> 1][q0], bh[n >> 1][q0 + 1]);
                }
        }
        __syncthreads();
    }

    // ---- epilogue ----
    const int rbase = m0 + mwarp + (lane >> 2);
    const int cbase = n0 + nwarp + (lane & 3) * 2;

    if (OUTF == 0) {
        float* C = Cf + (size_t)z * sC;
        #pragma unroll
        for (int mb = 0; mb < 4; ++mb) {
            #pragma unroll
            for (int n = 0; n < 8; ++n) {
                const int gc = cbase + n * 8;
                float bx = 0.0f, by = 0.0f;
                if (bias) { bx = bias[gc]; by = bias[gc + 1]; }
                const int r = rbase + mb * 16;
                float2 v0 = { acc[mb][n][0] + bx, acc[mb][n][1] + by };
                float2 v1 = { acc[mb][n][2] + bx, acc[mb][n][3] + by };
                *reinterpret_cast<float2*>(&C[(size_t)r * ldc + gc])       = v0;
                *reinterpret_cast<float2*>(&C[(size_t)(r + 8) * ldc + gc]) = v1;
            }
        }
    } else {
        __nv_bfloat16* CH = Chi + (size_t)z * sC;
        __nv_bfloat16* CL = Clo + (size_t)z * sC;
        #pragma unroll
        for (int mb = 0; mb < 4; ++mb) {
            #pragma unroll
            for (int n = 0; n < 8; ++n) {
                const int gc = cbase + n * 8;
                const int r  = rbase + mb * 16;
                #pragma unroll
                for (int half = 0; half < 2; ++half) {
                    const float v0 = acc[mb][n][half * 2 + 0];
                    const float v1 = acc[mb][n][half * 2 + 1];
                    const __nv_bfloat16 h0 = __float2bfloat16(v0);
                    const __nv_bfloat16 h1 = __float2bfloat16(v1);
                    __nv_bfloat162 ph; ph.x = h0; ph.y = h1;
                    __nv_bfloat162 pl;
                    pl.x = __float2bfloat16(v0 - __bfloat162float(h0));
                    pl.y = __float2bfloat16(v1 - __bfloat162float(h1));
                    const size_t off = (size_t)(r + half * 8) * ldc + gc;
                    *reinterpret_cast<__nv_bfloat162*>(&CH[off]) = ph;
                    *reinterpret_cast<__nv_bfloat162*>(&CL[off]) = pl;
                }
            }
        }
    }
}

// ===========================================================================
// wmma2 (128x128 CTA, 32x64 warp tiles) — kept for the small hw GEMM only.
// MODE 1 (SPLIT3), OUTF 1 (bf16 hi/lo out).
// ===========================================================================
__global__ __launch_bounds__(256)
void wmma2_hw(const __nv_bfloat16* __restrict__ a_hi, const __nv_bfloat16* __restrict__ a_lo,
              const __nv_bfloat16* __restrict__ b_hi, const __nv_bfloat16* __restrict__ b_lo,
              __nv_bfloat16* __restrict__ Chi, __nv_bfloat16* __restrict__ Clo,
              int K, int lda, int ldb, int ldc)
{
    constexpr uint32_t TSZ = 16384;
    constexpr uint32_t STG = 4 * TSZ;
    extern __shared__ __align__(128) char smem[];
    const uint32_t sbase = smem_u32(smem);

    const int t     = threadIdx.x;
    const int lane  = t & 31;
    const int warp  = t >> 5;
    const int mwarp = (warp >> 1) * 32;
    const int nwarp = (warp & 1) * 64;
    const int m0 = blockIdx.y * 128;
    const int n0 = blockIdx.x * 128;

    const __nv_bfloat16* Ah = a_hi + (size_t)m0 * lda;
    const __nv_bfloat16* Al = a_lo + (size_t)m0 * lda;
    const __nv_bfloat16* Bh = b_hi + (size_t)n0 * ldb;
    const __nv_bfloat16* Bl = b_lo + (size_t)n0 * ldb;

    const int NC = K >> 6;

    float acc[2][8][4];
    #pragma unroll
    for (int i = 0; i < 2; i++)
        #pragma unroll
        for (int j = 0; j < 8; j++)
            #pragma unroll
            for (int q = 0; q < 4; q++)
                acc[i][j][q] = 0.0f;

    auto load_stage = [&](int kc, uint32_t sb) {
        cp_tile<128>(Ah, lda, sb, t, kc);
        cp_tile<128>(Al, lda, sb + TSZ, t, kc);
        cp_tile<128>(Bh, ldb, sb + 2 * TSZ, t, kc);
        cp_tile<128>(Bl, ldb, sb + 3 * TSZ, t, kc);
        CP_COMMIT();
    };

    load_stage(0, sbase);

    for (int c = 0; c < NC; ++c) {
        const int buf = c & 1;
        if (c + 1 < NC) {
            load_stage(c + 1, sbase + ((c + 1) & 1) * STG);
            CP_WAIT(1);
        } else {
            CP_WAIT(0);
        }
        __syncthreads();

        const uint32_t S = sbase + buf * STG;

        #pragma unroll
        for (int ks = 0; ks < 4; ++ks) {
            uint32_t ah[2][4], al[2][4];
            #pragma unroll
            for (int mb = 0; mb < 2; ++mb) {
                const int row = mwarp + mb * 16 + (lane & 15);
                const int col = ks * 32 + ((lane >> 4) << 4);
                const uint32_t sw = (row << 7) + (col ^ ((row & 7) << 4));
                LDSM4(ah[mb][0], ah[mb][1], ah[mb][2], ah[mb][3], S + sw);
                LDSM4(al[mb][0], al[mb][1], al[mb][2], al[mb][3], S + TSZ + sw);
            }
            uint32_t bh[4][4], bl[4][4];
            #pragma unroll
            for (int nq = 0; nq < 4; ++nq) {
                const int row = nwarp + nq * 16 + ((lane >> 4) << 3) + (lane & 7);
                const int col = ks * 32 + (((lane >> 3) & 1) << 4);
                const uint32_t sw = (row << 7) + (col ^ ((row & 7) << 4));
                LDSM4(bh[nq][0], bh[nq][1], bh[nq][2], bh[nq][3], S + 2 * TSZ + sw);
                LDSM4(bl[nq][0], bl[nq][1], bl[nq][2], bl[nq][3], S + 3 * TSZ + sw);
            }
            #pragma unroll
            for (int mb = 0; mb < 2; ++mb)
                #pragma unroll
                for (int n = 0; n < 8; ++n) {
                    const int q0 = (n & 1) * 2;
                    MMA16816(acc[mb][n], ah[mb], bh[n >> 1][q0], bh[n >> 1][q0 + 1]);
                    MMA16816(acc[mb][n], ah[mb], bl[n >> 1][q0], bl[n >> 1][q0 + 1]);
                    MMA16816(acc[mb][n], al[mb], bh[n >> 1][q0], bh[n >> 1][q0 + 1]);
                }
        }
        __syncthreads();
    }

    const int rbase = m0 + mwarp + (lane >> 2);
    const int cbase = n0 + nwarp + (lane & 3) * 2;
    #pragma unroll
    for (int mb = 0; mb < 2; ++mb) {
        #pragma unroll
        for (int n = 0; n < 8; ++n) {
            const int gc = cbase + n * 8;
            const int r  = rbase + mb * 16;
            #pragma unroll
            for (int half = 0; half < 2; ++half) {
                const float v0 = acc[mb][n][half * 2 + 0];
                const float v1 = acc[mb][n][half * 2 + 1];
                const __nv_bfloat16 h0 = __float2bfloat16(v0);
                const __nv_bfloat16 h1 = __float2bfloat16(v1);
                __nv_bfloat162 ph; ph.x = h0; ph.y = h1;
                __nv_bfloat162 pl;
                pl.x = __float2bfloat16(v0 - __bfloat162float(h0));
                pl.y = __float2bfloat16(v1 - __bfloat162float(h1));
                const size_t off = (size_t)(r + half * 8) * ldc + gc;
                *reinterpret_cast<__nv_bfloat162*>(&Chi[off]) = ph;
                *reinterpret_cast<__nv_bfloat162*>(&Clo[off]) = pl;
            }
        }
    }
}

// ===========================================================================
// Prep kernels
// ===========================================================================
__global__ __launch_bounds__(256)
void adj_transpose(const float* __restrict__ adj, __nv_bfloat16* __restrict__ adjT)
{
    __shared__ float tile[32][33];
    const int b  = blockIdx.z;
    const int j0 = blockIdx.x * 32;
    const int n0 = blockIdx.y * 32;
    const float* src = adj + (size_t)b * NN * NN;
    __nv_bfloat16* dst = adjT + (size_t)b * NN * NN;
    const int tx = threadIdx.x & 31, ty = threadIdx.x >> 5;
    #pragma unroll
    for (int r = ty; r < 32; r += 8)
        tile[r][tx] = src[(size_t)(j0 + r) * NN + n0 + tx];
    __syncthreads();
    #pragma unroll
    for (int r = ty; r < 32; r += 8)
        dst[(size_t)(n0 + r) * NN + j0 + tx] = __float2bfloat16(tile[tx][r]);
}

__global__ __launch_bounds__(256)
void split2(const float* __restrict__ x,
            __nv_bfloat16* __restrict__ hi, __nv_bfloat16* __restrict__ lo)
{
    const int i = blockIdx.x * blockDim.x + threadIdx.x;
    const float v = x[i];
    const __nv_bfloat16 h = __float2bfloat16(v);
    hi[i] = h;
    lo[i] = __float2bfloat16(v - __bfloat162float(h));
}

// weight[l] fp32 [C][C] (W[c][d]) -> WT hi/lo bf16 [l][d][c]
__global__ __launch_bounds__(256)
void wT_split(const float* __restrict__ W,
              __nv_bfloat16* __restrict__ hi, __nv_bfloat16* __restrict__ lo)
{
    __shared__ float tile[32][33];
    const int l  = blockIdx.z;
    const int c0 = blockIdx.x * 32;
    const int d0 = blockIdx.y * 32;
    const float* src = W + (size_t)l * CC * CC;
    const size_t ob = (size_t)l * CC * CC;
    const int tx = threadIdx.x & 31, ty = threadIdx.x >> 5;
    #pragma unroll
    for (int r = ty; r < 32; r += 8)
        tile[r][tx] = src[(size_t)(c0 + r) * CC + d0 + tx];
    __syncthreads();
    #pragma unroll
    for (int r = ty; r < 32; r += 8) {
        const float v = tile[tx][r];
        const __nv_bfloat16 h = __float2bfloat16(v);
        hi[ob + (size_t)(d0 + r) * CC + c0 + tx] = h;
        lo[ob + (size_t)(d0 + r) * CC + c0 + tx] = __float2bfloat16(v - __bfloat162float(h));
    }
}

// ===========================================================================
// Fused GRU elementwise (+ optional bf16 hi/lo output for next layer)
// ===========================================================================
__global__ __launch_bounds__(256)
void gru_elem2(const float* __restrict__ gx, const float* __restrict__ gh,
               const float* __restrict__ h, float* __restrict__ hout,
               __nv_bfloat16* __restrict__ hhi, __nv_bfloat16* __restrict__ hlo,
               const float* __restrict__ mask, int applyMask, int writeSplit)
{
    const int idx = blockIdx.x * blockDim.x + threadIdx.x;
    const int r = idx >> 7;
    const int c = idx & 127;

    const long gbase = (long)r * (3 * CC);
    const float xr = gx[gbase + c];
    const float xz = gx[gbase + CC + c];
    const float xn = gx[gbase + 2 * CC + c];
    const float hr = gh[gbase + c];
    const float hz = gh[gbase + CC + c];
    const float hn = gh[gbase + 2 * CC + c];

    const float rg = 1.0f / (1.0f + __expf(-(xr + hr)));
    const float zg = 1.0f / (1.0f + __expf(-(xz + hz)));
    const float ng = tanhf(xn + rg * hn);
    float hnew = (1.0f - zg) * ng + zg * h[idx];
    hout[idx] = applyMask ? hnew * mask[r] : hnew;
    if (writeSplit) {
        const __nv_bfloat16 hb = __float2bfloat16(hnew);
        hhi[idx] = hb;
        hlo[idx] = __float2bfloat16(hnew - __bfloat162float(hb));
    }
}

// ===========================================================================
#define SMEM_ADJ3    (2 * (32768 + 2 * 16384))           // 128 KB
#define SMEM_SPLIT3B (2 * (2 * 32768 + 2 * 16384))       // 192 KB
#define SMEM_HW      (2 * 4 * 16384)                     // 128 KB

extern "C" void kernel_launch(void* const* d_in, const int* in_sizes, int n_in,
                              void* d_out, int out_size)
{
    const float* x      = (const float*)d_in[0];
    const float* adj    = (const float*)d_in[1];
    const float* mask   = (const float*)d_in[2];
    const float* weight = (const float*)d_in[3];
    const float* w_ih   = (const float*)d_in[4];
    const float* w_hh   = (const float*)d_in[5];
    const float* b_ih   = (const float*)d_in[6];
    const float* b_hh   = (const float*)d_in[7];
    float* out = (float*)d_out;

    float *p_h0, *p_h1, *p_gx, *p_gh;
    __nv_bfloat16 *p_adjT, *p_hwhi, *p_hwlo, *p_hhi, *p_hlo, *p_mhi, *p_mlo;
    __nv_bfloat16 *p_wThi, *p_wTlo, *p_wihhi, *p_wihlo, *p_whhhi, *p_whhlo;
    cudaGetSymbolAddress((void**)&p_h0, g_h0);
    cudaGetSymbolAddress((void**)&p_h1, g_h1);
    cudaGetSymbolAddress((void**)&p_gx, g_gx);
    cudaGetSymbolAddress((void**)&p_gh, g_gh);
    cudaGetSymbolAddress((void**)&p_adjT, g_adjT);
    cudaGetSymbolAddress((void**)&p_hwhi, g_hwT_hi);
    cudaGetSymbolAddress((void**)&p_hwlo, g_hwT_lo);
    cudaGetSymbolAddress((void**)&p_hhi, g_hA_hi);
    cudaGetSymbolAddress((void**)&p_hlo, g_hA_lo);
    cudaGetSymbolAddress((void**)&p_mhi, g_mA_hi);
    cudaGetSymbolAddress((void**)&p_mlo, g_mA_lo);
    cudaGetSymbolAddress((void**)&p_wThi, g_wT_hi);
    cudaGetSymbolAddress((void**)&p_wTlo, g_wT_lo);
    cudaGetSymbolAddress((void**)&p_wihhi, g_wih_hi);
    cudaGetSymbolAddress((void**)&p_wihlo, g_wih_lo);
    cudaGetSymbolAddress((void**)&p_whhhi, g_whh_hi);
    cudaGetSymbolAddress((void**)&p_whhlo, g_whh_lo);

    cudaFuncSetAttribute(wmma3<0, 1>, cudaFuncAttributeMaxDynamicSharedMemorySize, SMEM_ADJ3);
    cudaFuncSetAttribute(wmma3<1, 0>, cudaFuncAttributeMaxDynamicSharedMemorySize, SMEM_SPLIT3B);
    cudaFuncSetAttribute(wmma2_hw,    cudaFuncAttributeMaxDynamicSharedMemorySize, SMEM_HW);

    float* hbuf[2] = { p_h0, p_h1 };

    // ---- once per call ----
    adj_transpose<<<dim3(NN / 32, NN / 32, BB), 256>>>(adj, p_adjT);
    wT_split<<<dim3(CC / 32, CC / 32, LL), 256>>>(weight, p_wThi, p_wTlo);
    split2<<<(LL * 3 * CC * CC) / 256, 256>>>(w_ih, p_wihhi, p_wihlo);
    split2<<<(LL * 3 * CC * CC) / 256, 256>>>(w_hh, p_whhhi, p_whhlo);
    split2<<<HSZ / 256, 256>>>(x, p_hhi, p_hlo);     // h0 = x

    for (int l = 0; l < LL; l++) {
        const float* hin  = (l == 0) ? x : hbuf[(l + 1) & 1];
        float*       hout = (l == LL - 1) ? out : hbuf[l & 1];
        const long loffW  = (long)l * CC * CC;
        const long loffG  = (long)l * 3 * CC * CC;

        // 1) hwT[d][b*N+j] = sum_c WT[d][c] * h[j][c]  -> bf16 hi/lo
        wmma2_hw<<<dim3(ROWS / 128, 1, 1), 256, SMEM_HW>>>(
            p_wThi + loffW, p_wTlo + loffW, p_hhi, p_hlo,
            p_hwhi, p_hwlo, CC, CC, CC, ROWS);

        // 2) m[b][n][d] = sum_j adjT[b][n][j] * (hwT_hi+hwT_lo)[d][b*N+j] -> bf16 hi/lo
        wmma3<0, 1><<<dim3(1, NN / 256, BB), 256, SMEM_ADJ3>>>(
            p_adjT, p_adjT, p_hwhi, p_hwlo,
            nullptr, p_mhi, p_mlo,
            NN, NN, ROWS, CC,
            (long)NN * NN, (long)NN, (long)NN * CC, nullptr);

        // 3) gx = m @ w_ih^T + b_ih   (fp32)
        wmma3<1, 0><<<dim3(3, ROWS / 256, 1), 256, SMEM_SPLIT3B>>>(
            p_mhi, p_mlo, p_wihhi + loffG, p_wihlo + loffG,
            p_gx, nullptr, nullptr,
            CC, CC, CC, 3 * CC, 0, 0, 0, b_ih + (long)l * 3 * CC);

        // 4) gh = h @ w_hh^T + b_hh   (fp32)
        wmma3<1, 0><<<dim3(3, ROWS / 256, 1), 256, SMEM_SPLIT3B>>>(
            p_hhi, p_hlo, p_whhhi + loffG, p_whhlo + loffG,
            p_gh, nullptr, nullptr,
            CC, CC, CC, 3 * CC, 0, 0, 0, b_hh + (long)l * 3 * CC);

        // 5) GRU elementwise (+ split h for next layer)
        gru_elem2<<<(ROWS * CC) / 256, 256>>>(
            p_gx, p_gh, hin, hout, p_hhi, p_hlo, mask,
            (l == LL - 1) ? 1 : 0, (l == LL - 1) ? 0 : 1);
    }
}

// round 7
// speedup vs baseline: 2.7466x; 1.0721x over previous
#include <cuda_runtime.h>
#include <cuda_fp16.h>
#include <cstdint>

// Problem constants: B=32, N=1024, C=128, L=4
#define BB 32
#define NN 1024
#define CC 128
#define LL 4
#define ROWS (BB * NN)          // 32768
#define HSZ  (ROWS * CC)
#define GSZ  (ROWS * 3 * CC)

// fp32 scratch
__device__ __align__(16) float g_gx[GSZ];
__device__ __align__(16) float g_gh[GSZ];
// fp16 scratch
__device__ __align__(16) __half g_adjT[(size_t)BB * NN * NN];   // [b][n][j] exact
__device__ __align__(16) __half g_hwT_hi[HSZ];                  // [d][b*N+j]
__device__ __align__(16) __half g_hwT_lo[HSZ];
__device__ __align__(16) __half g_hA_hi[HSZ];                   // h splits (ping)
__device__ __align__(16) __half g_hA_lo[HSZ];
__device__ __align__(16) __half g_hB_hi[HSZ];                   // h splits (pong)
__device__ __align__(16) __half g_hB_lo[HSZ];
__device__ __align__(16) __half g_mA_hi[HSZ];                   // m splits
__device__ __align__(16) __half g_mA_lo[HSZ];
__device__ __align__(16) __half g_wT_hi[LL * CC * CC];          // [l][d][c]
__device__ __align__(16) __half g_wT_lo[LL * CC * CC];
__device__ __align__(16) __half g_wih_hi[LL * 3 * CC * CC];
__device__ __align__(16) __half g_wih_lo[LL * 3 * CC * CC];
__device__ __align__(16) __half g_whh_hi[LL * 3 * CC * CC];
__device__ __align__(16) __half g_whh_lo[LL * 3 * CC * CC];

// ===========================================================================
// helpers
// ===========================================================================
__device__ __forceinline__ uint32_t smem_u32(const void* p) {
    uint32_t a;
    asm("{ .reg .u64 t; cvta.to.shared.u64 t, %1; cvt.u32.u64 %0, t; }"
        : "=r"(a) : "l"(p));
    return a;
}
__device__ __forceinline__ void cp16(uint32_t s, const void* g) {
    asm volatile("cp.async.cg.shared.global [%0], [%1], 16;" :: "r"(s), "l"(g));
}
#define CP_COMMIT() asm volatile("cp.async.commit_group;" ::: "memory")
#define CP_WAIT(n)  asm volatile("cp.async.wait_group %0;" :: "n"(n) : "memory")

#define LDSM4(R0, R1, R2, R3, ADDR)                                          \
    asm volatile("ldmatrix.sync.aligned.m8n8.x4.shared.b16 {%0,%1,%2,%3}, [%4];" \
                 : "=r"(R0), "=r"(R1), "=r"(R2), "=r"(R3) : "r"(ADDR))

#define MMA16816(D, A, B0, B1)                                               \
    asm volatile(                                                            \
        "mma.sync.aligned.m16n8k16.row.col.f32.f16.f16.f32 "                 \
        "{%0,%1,%2,%3},{%4,%5,%6,%7},{%8,%9},{%0,%1,%2,%3};"                 \
        : "+f"((D)[0]), "+f"((D)[1]), "+f"((D)[2]), "+f"((D)[3])             \
        : "r"((A)[0]), "r"((A)[1]), "r"((A)[2]), "r"((A)[3]),                \
          "r"(B0), "r"(B1))

// Load an R-row x 64-col fp16 tile (128B rows, XOR-16B swizzle) via cp.async.
template <int R>
__device__ __forceinline__ void cp_tile(const __half* __restrict__ g,
                                        int stride, uint32_t sdst, int t, int kc)
{
    #pragma unroll
    for (int u = 0; u < R / 32; ++u) {
        const int unit = t + u * 256;
        const int row  = unit >> 3;
        const int c16  = unit & 7;
        const uint32_t sw = ((row << 7) + (c16 << 4)) ^ ((row & 7) << 4);
        cp16(sdst + sw, g + (size_t)row * stride + (kc << 6) + (c16 << 3));
    }
}

// ===========================================================================
// adj GEMM: CTA 256x128, warp 64x64, 3-stage pipeline.
//   C = A @ (Bhi + Blo)^T  (A exact fp16), out: fp16 hi/lo split
// A: [M][K] stride lda, per-batch stride sA; B rows [N][K] stride ldb.
// ===========================================================================
__global__ __launch_bounds__(256)
void adj_mma(const __half* __restrict__ a, const __half* __restrict__ b_hi,
             const __half* __restrict__ b_lo,
             __half* __restrict__ Chi, __half* __restrict__ Clo,
             int K, int lda, int ldb, int ldc,
             long sA, long sB, long sC)
{
    constexpr uint32_t ATSZ = 32768;
    constexpr uint32_t BTSZ = 16384;
    constexpr uint32_t STG  = ATSZ + 2 * BTSZ;   // 64 KB, 3 stages = 192 KB
    extern __shared__ __align__(128) char smem[];
    const uint32_t sbase = smem_u32(smem);

    const int t     = threadIdx.x;
    const int lane  = t & 31;
    const int warp  = t >> 5;
    const int mwarp = (warp >> 1) * 64;
    const int nwarp = (warp & 1) * 64;
    const int m0 = blockIdx.y * 256;
    const int n0 = blockIdx.x * 128;
    const int z  = blockIdx.z;

    const __half* Ag = a    + (size_t)z * sA + (size_t)m0 * lda;
    const __half* Bh = b_hi + (size_t)z * sB + (size_t)n0 * ldb;
    const __half* Bl = b_lo + (size_t)z * sB + (size_t)n0 * ldb;

    const int NC = K >> 6;

    float acc[4][8][4];
    #pragma unroll
    for (int i = 0; i < 4; i++)
        #pragma unroll
        for (int j = 0; j < 8; j++)
            #pragma unroll
            for (int q = 0; q < 4; q++)
                acc[i][j][q] = 0.0f;

    auto load_stage = [&](int kc, uint32_t sb) {
        cp_tile<256>(Ag, lda, sb, t, kc);
        cp_tile<128>(Bh, ldb, sb + ATSZ, t, kc);
        cp_tile<128>(Bl, ldb, sb + ATSZ + BTSZ, t, kc);
        CP_COMMIT();
    };

    load_stage(0, sbase);
    load_stage(1, sbase + STG);

    for (int c = 0; c < NC; ++c) {
        const int nxt = c + 2;
        if (nxt < NC) load_stage(nxt, sbase + (nxt % 3) * STG);
        const int nleft = NC - 1 - c;
        if (nleft >= 2)      CP_WAIT(2);
        else if (nleft == 1) CP_WAIT(1);
        else                 CP_WAIT(0);
        __syncthreads();

        const uint32_t S = sbase + (c % 3) * STG;
        const uint32_t Bb = S + ATSZ;

        #pragma unroll
        for (int ks = 0; ks < 4; ++ks) {
            uint32_t ah[4][4];
            #pragma unroll
            for (int mb = 0; mb < 4; ++mb) {
                const int row = mwarp + mb * 16 + (lane & 15);
                const int col = ks * 32 + ((lane >> 4) << 4);
                const uint32_t sw = (row << 7) + (col ^ ((row & 7) << 4));
                LDSM4(ah[mb][0], ah[mb][1], ah[mb][2], ah[mb][3], S + sw);
            }
            uint32_t bh[4][4], bl[4][4];
            #pragma unroll
            for (int nq = 0; nq < 4; ++nq) {
                const int row = nwarp + nq * 16 + ((lane >> 4) << 3) + (lane & 7);
                const int col = ks * 32 + (((lane >> 3) & 1) << 4);
                const uint32_t sw = (row << 7) + (col ^ ((row & 7) << 4));
                LDSM4(bh[nq][0], bh[nq][1], bh[nq][2], bh[nq][3], Bb + sw);
                LDSM4(bl[nq][0], bl[nq][1], bl[nq][2], bl[nq][3], Bb + BTSZ + sw);
            }
            #pragma unroll
            for (int mb = 0; mb < 4; ++mb)
                #pragma unroll
                for (int n = 0; n < 8; ++n) {
                    const int q0 = (n & 1) * 2;
                    MMA16816(acc[mb][n], ah[mb], bh[n >> 1][q0], bh[n >> 1][q0 + 1]);
                    MMA16816(acc[mb][n], ah[mb], bl[n >> 1][q0], bl[n >> 1][q0 + 1]);
                }
        }
        __syncthreads();
    }

    // epilogue: fp16 hi/lo
    const int rbase = m0 + mwarp + (lane >> 2);
    const int cbase = n0 + nwarp + (lane & 3) * 2;
    __half* CH = Chi + (size_t)z * sC;
    __half* CL = Clo + (size_t)z * sC;
    #pragma unroll
    for (int mb = 0; mb < 4; ++mb) {
        #pragma unroll
        for (int n = 0; n < 8; ++n) {
            const int gc = cbase + n * 8;
            const int r  = rbase + mb * 16;
            #pragma unroll
            for (int hf = 0; hf < 2; ++hf) {
                const float v0 = acc[mb][n][hf * 2 + 0];
                const float v1 = acc[mb][n][hf * 2 + 1];
                const __half h0 = __float2half_rn(v0);
                const __half h1 = __float2half_rn(v1);
                __half2 ph; ph.x = h0; ph.y = h1;
                __half2 pl;
                pl.x = __float2half_rn(v0 - __half2float(h0));
                pl.y = __float2half_rn(v1 - __half2float(h1));
                const size_t off = (size_t)(r + hf * 8) * ldc + gc;
                *reinterpret_cast<__half2*>(&CH[off]) = ph;
                *reinterpret_cast<__half2*>(&CL[off]) = pl;
            }
        }
    }
}

// ===========================================================================
// Merged gate GEMMs: grid.z selects (A,B,C,bias) set.
//   C = Ahi@Bhi^T + Ahi@Blo^T + Alo@Bhi^T + bias   (fp32 out)
// CTA 256x128, warp 64x64, 2-stage. K=128 (NC=2). ldc = 384.
// ===========================================================================
__global__ __launch_bounds__(256)
void gate_mma(const __half* __restrict__ a0h, const __half* __restrict__ a0l,
              const __half* __restrict__ b0h, const __half* __restrict__ b0l,
              float* __restrict__ C0, const float* __restrict__ bias0,
              const __half* __restrict__ a1h, const __half* __restrict__ a1l,
              const __half* __restrict__ b1h, const __half* __restrict__ b1l,
              float* __restrict__ C1, const float* __restrict__ bias1)
{
    constexpr uint32_t ATSZ = 32768;
    constexpr uint32_t BTSZ = 16384;
    constexpr uint32_t STG  = 2 * ATSZ + 2 * BTSZ;   // 96 KB, 2 stages = 192 KB
    extern __shared__ __align__(128) char smem[];
    const uint32_t sbase = smem_u32(smem);

    const int t     = threadIdx.x;
    const int lane  = t & 31;
    const int warp  = t >> 5;
    const int mwarp = (warp >> 1) * 64;
    const int nwarp = (warp & 1) * 64;
    const int m0 = blockIdx.y * 256;
    const int n0 = blockIdx.x * 128;
    const int z  = blockIdx.z;

    const __half* Ah = (z == 0 ? a0h : a1h) + (size_t)m0 * CC;
    const __half* Al = (z == 0 ? a0l : a1l) + (size_t)m0 * CC;
    const __half* Bh = (z == 0 ? b0h : b1h) + (size_t)n0 * CC;
    const __half* Bl = (z == 0 ? b0l : b1l) + (size_t)n0 * CC;
    float* C = (z == 0 ? C0 : C1);
    const float* bias = (z == 0 ? bias0 : bias1);

    constexpr int NC = 2;   // K = 128

    float acc[4][8][4];
    #pragma unroll
    for (int i = 0; i < 4; i++)
        #pragma unroll
        for (int j = 0; j < 8; j++)
            #pragma unroll
            for (int q = 0; q < 4; q++)
                acc[i][j][q] = 0.0f;

    auto load_stage = [&](int kc, uint32_t sb) {
        cp_tile<256>(Ah, CC, sb, t, kc);
        cp_tile<256>(Al, CC, sb + ATSZ, t, kc);
        cp_tile<128>(Bh, CC, sb + 2 * ATSZ, t, kc);
        cp_tile<128>(Bl, CC, sb + 2 * ATSZ + BTSZ, t, kc);
        CP_COMMIT();
    };

    load_stage(0, sbase);
    load_stage(1, sbase + STG);

    #pragma unroll
    for (int c = 0; c < NC; ++c) {
        if (c == 0) CP_WAIT(1); else CP_WAIT(0);
        __syncthreads();

        const uint32_t S = sbase + c * STG;
        const uint32_t Bb = S + 2 * ATSZ;

        #pragma unroll
        for (int ks = 0; ks < 4; ++ks) {
            uint32_t ah[4][4], al[4][4];
            #pragma unroll
            for (int mb = 0; mb < 4; ++mb) {
                const int row = mwarp + mb * 16 + (lane & 15);
                const int col = ks * 32 + ((lane >> 4) << 4);
                const uint32_t sw = (row << 7) + (col ^ ((row & 7) << 4));
                LDSM4(ah[mb][0], ah[mb][1], ah[mb][2], ah[mb][3], S + sw);
                LDSM4(al[mb][0], al[mb][1], al[mb][2], al[mb][3], S + ATSZ + sw);
            }
            uint32_t bh[4][4], bl[4][4];
            #pragma unroll
            for (int nq = 0; nq < 4; ++nq) {
                const int row = nwarp + nq * 16 + ((lane >> 4) << 3) + (lane & 7);
                const int col = ks * 32 + (((lane >> 3) & 1) << 4);
                const uint32_t sw = (row << 7) + (col ^ ((row & 7) << 4));
                LDSM4(bh[nq][0], bh[nq][1], bh[nq][2], bh[nq][3], Bb + sw);
                LDSM4(bl[nq][0], bl[nq][1], bl[nq][2], bl[nq][3], Bb + BTSZ + sw);
            }
            #pragma unroll
            for (int mb = 0; mb < 4; ++mb)
                #pragma unroll
                for (int n = 0; n < 8; ++n) {
                    const int q0 = (n & 1) * 2;
                    MMA16816(acc[mb][n], ah[mb], bh[n >> 1][q0], bh[n >> 1][q0 + 1]);
                    MMA16816(acc[mb][n], ah[mb], bl[n >> 1][q0], bl[n >> 1][q0 + 1]);
                    MMA16816(acc[mb][n], al[mb], bh[n >> 1][q0], bh[n >> 1][q0 + 1]);
                }
        }
        __syncthreads();
    }

    const int rbase = m0 + mwarp + (lane >> 2);
    const int cbase = n0 + nwarp + (lane & 3) * 2;
    #pragma unroll
    for (int mb = 0; mb < 4; ++mb) {
        #pragma unroll
        for (int n = 0; n < 8; ++n) {
            const int gc = cbase + n * 8;
            const float bx = bias[gc];
            const float by = bias[gc + 1];
            const int r = rbase + mb * 16;
            float2 v0 = { acc[mb][n][0] + bx, acc[mb][n][1] + by };
            float2 v1 = { acc[mb][n][2] + bx, acc[mb][n][3] + by };
            *reinterpret_cast<float2*>(&C[(size_t)r * (3 * CC) + gc])       = v0;
            *reinterpret_cast<float2*>(&C[(size_t)(r + 8) * (3 * CC) + gc]) = v1;
        }
    }
}

// ===========================================================================
// wmma2_hw (128x128 CTA): 3-product fp16 split GEMM for hw (near-exact).
// C = Ahi@Bhi + Ahi@Blo + Alo@Bhi  -> fp16 hi/lo out (transposed layout)
// ===========================================================================
__global__ __launch_bounds__(256)
void wmma2_hw(const __half* __restrict__ a_hi, const __half* __restrict__ a_lo,
              const __half* __restrict__ b_hi, const __half* __restrict__ b_lo,
              __half* __restrict__ Chi, __half* __restrict__ Clo,
              int K, int lda, int ldb, int ldc)
{
    constexpr uint32_t TSZ = 16384;
    constexpr uint32_t STG = 4 * TSZ;
    extern __shared__ __align__(128) char smem[];
    const uint32_t sbase = smem_u32(smem);

    const int t     = threadIdx.x;
    const int lane  = t & 31;
    const int warp  = t >> 5;
    const int mwarp = (warp >> 1) * 32;
    const int nwarp = (warp & 1) * 64;
    const int m0 = blockIdx.y * 128;
    const int n0 = blockIdx.x * 128;

    const __half* Ah = a_hi + (size_t)m0 * lda;
    const __half* Al = a_lo + (size_t)m0 * lda;
    const __half* Bh = b_hi + (size_t)n0 * ldb;
    const __half* Bl = b_lo + (size_t)n0 * ldb;

    const int NC = K >> 6;

    float acc[2][8][4];
    #pragma unroll
    for (int i = 0; i < 2; i++)
        #pragma unroll
        for (int j = 0; j < 8; j++)
            #pragma unroll
            for (int q = 0; q < 4; q++)
                acc[i][j][q] = 0.0f;

    auto load_stage = [&](int kc, uint32_t sb) {
        cp_tile<128>(Ah, lda, sb, t, kc);
        cp_tile<128>(Al, lda, sb + TSZ, t, kc);
        cp_tile<128>(Bh, ldb, sb + 2 * TSZ, t, kc);
        cp_tile<128>(Bl, ldb, sb + 3 * TSZ, t, kc);
        CP_COMMIT();
    };

    load_stage(0, sbase);

    for (int c = 0; c < NC; ++c) {
        const int buf = c & 1;
        if (c + 1 < NC) {
            load_stage(c + 1, sbase + ((c + 1) & 1) * STG);
            CP_WAIT(1);
        } else {
            CP_WAIT(0);
        }
        __syncthreads();

        const uint32_t S = sbase + buf * STG;

        #pragma unroll
        for (int ks = 0; ks < 4; ++ks) {
            uint32_t ah[2][4], al[2][4];
            #pragma unroll
            for (int mb = 0; mb < 2; ++mb) {
                const int row = mwarp + mb * 16 + (lane & 15);
                const int col = ks * 32 + ((lane >> 4) << 4);
                const uint32_t sw = (row << 7) + (col ^ ((row & 7) << 4));
                LDSM4(ah[mb][0], ah[mb][1], ah[mb][2], ah[mb][3], S + sw);
                LDSM4(al[mb][0], al[mb][1], al[mb][2], al[mb][3], S + TSZ + sw);
            }
            uint32_t bh[4][4], bl[4][4];
            #pragma unroll
            for (int nq = 0; nq < 4; ++nq) {
                const int row = nwarp + nq * 16 + ((lane >> 4) << 3) + (lane & 7);
                const int col = ks * 32 + (((lane >> 3) & 1) << 4);
                const uint32_t sw = (row << 7) + (col ^ ((row & 7) << 4));
                LDSM4(bh[nq][0], bh[nq][1], bh[nq][2], bh[nq][3], S + 2 * TSZ + sw);
                LDSM4(bl[nq][0], bl[nq][1], bl[nq][2], bl[nq][3], S + 3 * TSZ + sw);
            }
            #pragma unroll
            for (int mb = 0; mb < 2; ++mb)
                #pragma unroll
                for (int n = 0; n < 8; ++n) {
                    const int q0 = (n & 1) * 2;
                    MMA16816(acc[mb][n], ah[mb], bh[n >> 1][q0], bh[n >> 1][q0 + 1]);
                    MMA16816(acc[mb][n], ah[mb], bl[n >> 1][q0], bl[n >> 1][q0 + 1]);
                    MMA16816(acc[mb][n], al[mb], bh[n >> 1][q0], bh[n >> 1][q0 + 1]);
                }
        }
        __syncthreads();
    }

    const int rbase = m0 + mwarp + (lane >> 2);
    const int cbase = n0 + nwarp + (lane & 3) * 2;
    #pragma unroll
    for (int mb = 0; mb < 2; ++mb) {
        #pragma unroll
        for (int n = 0; n < 8; ++n) {
            const int gc = cbase + n * 8;
            const int r  = rbase + mb * 16;
            #pragma unroll
            for (int hf = 0; hf < 2; ++hf) {
                const float v0 = acc[mb][n][hf * 2 + 0];
                const float v1 = acc[mb][n][hf * 2 + 1];
                const __half h0 = __float2half_rn(v0);
                const __half h1 = __float2half_rn(v1);
                __half2 ph; ph.x = h0; ph.y = h1;
                __half2 pl;
                pl.x = __float2half_rn(v0 - __half2float(h0));
                pl.y = __float2half_rn(v1 - __half2float(h1));
                const size_t off = (size_t)(r + hf * 8) * ldc + gc;
                *reinterpret_cast<__half2*>(&Chi[off]) = ph;
                *reinterpret_cast<__half2*>(&Clo[off]) = pl;
            }
        }
    }
}

// ===========================================================================
// Prep kernels
// ===========================================================================
__global__ __launch_bounds__(256)
void adj_transpose(const float* __restrict__ adj, __half* __restrict__ adjT)
{
    __shared__ float tile[32][33];
    const int b  = blockIdx.z;
    const int j0 = blockIdx.x * 32;
    const int n0 = blockIdx.y * 32;
    const float* src = adj + (size_t)b * NN * NN;
    __half* dst = adjT + (size_t)b * NN * NN;
    const int tx = threadIdx.x & 31, ty = threadIdx.x >> 5;
    #pragma unroll
    for (int r = ty; r < 32; r += 8)
        tile[r][tx] = src[(size_t)(j0 + r) * NN + n0 + tx];
    __syncthreads();
    #pragma unroll
    for (int r = ty; r < 32; r += 8)
        dst[(size_t)(n0 + r) * NN + j0 + tx] = __float2half_rn(tile[tx][r]);
}

__global__ __launch_bounds__(256)
void split2(const float* __restrict__ x,
            __half* __restrict__ hi, __half* __restrict__ lo)
{
    const int i = blockIdx.x * blockDim.x + threadIdx.x;
    const float v = x[i];
    const __half h = __float2half_rn(v);
    hi[i] = h;
    lo[i] = __float2half_rn(v - __half2float(h));
}

// weight[l] fp32 [C][C] (W[c][d]) -> WT hi/lo fp16 [l][d][c]
__global__ __launch_bounds__(256)
void wT_split(const float* __restrict__ W,
              __half* __restrict__ hi, __half* __restrict__ lo)
{
    __shared__ float tile[32][33];
    const int l  = blockIdx.z;
    const int c0 = blockIdx.x * 32;
    const int d0 = blockIdx.y * 32;
    const float* src = W + (size_t)l * CC * CC;
    const size_t ob = (size_t)l * CC * CC;
    const int tx = threadIdx.x & 31, ty = threadIdx.x >> 5;
    #pragma unroll
    for (int r = ty; r < 32; r += 8)
        tile[r][tx] = src[(size_t)(c0 + r) * CC + d0 + tx];
    __syncthreads();
    #pragma unroll
    for (int r = ty; r < 32; r += 8) {
        const float v = tile[tx][r];
        const __half h = __float2half_rn(v);
        hi[ob + (size_t)(d0 + r) * CC + c0 + tx] = h;
        lo[ob + (size_t)(d0 + r) * CC + c0 + tx] = __float2half_rn(v - __half2float(h));
    }
}

// ===========================================================================
// Fused GRU elementwise: h stored as fp16 hi/lo splits only.
// ===========================================================================
__global__ __launch_bounds__(256)
void gru_elem3(const float* __restrict__ gx, const float* __restrict__ gh,
               const __half* __restrict__ hhi_in, const __half* __restrict__ hlo_in,
               __half* __restrict__ hhi_out, __half* __restrict__ hlo_out,
               float* __restrict__ outF,
               const float* __restrict__ mask, int isLast)
{
    const int idx = blockIdx.x * blockDim.x + threadIdx.x;
    const int r = idx >> 7;
    const int c = idx & 127;

    const long gbase = (long)r * (3 * CC);
    const float xr = gx[gbase + c];
    const float xz = gx[gbase + CC + c];
    const float xn = gx[gbase + 2 * CC + c];
    const float hr = gh[gbase + c];
    const float hz = gh[gbase + CC + c];
    const float hn = gh[gbase + 2 * CC + c];

    const float h = __half2float(hhi_in[idx]) + __half2float(hlo_in[idx]);

    const float rg = 1.0f / (1.0f + __expf(-(xr + hr)));
    const float zg = 1.0f / (1.0f + __expf(-(xz + hz)));
    const float ng = tanhf(xn + rg * hn);
    const float hnew = (1.0f - zg) * ng + zg * h;

    if (isLast) {
        outF[idx] = hnew * mask[r];
    } else {
        const __half hb = __float2half_rn(hnew);
        hhi_out[idx] = hb;
        hlo_out[idx] = __float2half_rn(hnew - __half2float(hb));
    }
}

// ===========================================================================
#define SMEM_ADJ   (3 * (32768 + 2 * 16384))         // 192 KB (3 stages)
#define SMEM_GATE  (2 * (2 * 32768 + 2 * 16384))     // 192 KB (2 stages)
#define SMEM_HW    (2 * 4 * 16384)                   // 128 KB

extern "C" void kernel_launch(void* const* d_in, const int* in_sizes, int n_in,
                              void* d_out, int out_size)
{
    const float* x      = (const float*)d_in[0];
    const float* adj    = (const float*)d_in[1];
    const float* mask   = (const float*)d_in[2];
    const float* weight = (const float*)d_in[3];
    const float* w_ih   = (const float*)d_in[4];
    const float* w_hh   = (const float*)d_in[5];
    const float* b_ih   = (const float*)d_in[6];
    const float* b_hh   = (const float*)d_in[7];
    float* out = (float*)d_out;

    float *p_gx, *p_gh;
    __half *p_adjT, *p_hwhi, *p_hwlo, *p_mhi, *p_mlo;
    __half *p_hAhi, *p_hAlo, *p_hBhi, *p_hBlo;
    __half *p_wThi, *p_wTlo, *p_wihhi, *p_wihlo, *p_whhhi, *p_whhlo;
    cudaGetSymbolAddress((void**)&p_gx, g_gx);
    cudaGetSymbolAddress((void**)&p_gh, g_gh);
    cudaGetSymbolAddress((void**)&p_adjT, g_adjT);
    cudaGetSymbolAddress((void**)&p_hwhi, g_hwT_hi);
    cudaGetSymbolAddress((void**)&p_hwlo, g_hwT_lo);
    cudaGetSymbolAddress((void**)&p_hAhi, g_hA_hi);
    cudaGetSymbolAddress((void**)&p_hAlo, g_hA_lo);
    cudaGetSymbolAddress((void**)&p_hBhi, g_hB_hi);
    cudaGetSymbolAddress((void**)&p_hBlo, g_hB_lo);
    cudaGetSymbolAddress((void**)&p_mhi, g_mA_hi);
    cudaGetSymbolAddress((void**)&p_mlo, g_mA_lo);
    cudaGetSymbolAddress((void**)&p_wThi, g_wT_hi);
    cudaGetSymbolAddress((void**)&p_wTlo, g_wT_lo);
    cudaGetSymbolAddress((void**)&p_wihhi, g_wih_hi);
    cudaGetSymbolAddress((void**)&p_wihlo, g_wih_lo);
    cudaGetSymbolAddress((void**)&p_whhhi, g_whh_hi);
    cudaGetSymbolAddress((void**)&p_whhlo, g_whh_lo);

    cudaFuncSetAttribute(adj_mma,  cudaFuncAttributeMaxDynamicSharedMemorySize, SMEM_ADJ);
    cudaFuncSetAttribute(gate_mma, cudaFuncAttributeMaxDynamicSharedMemorySize, SMEM_GATE);
    cudaFuncSetAttribute(wmma2_hw, cudaFuncAttributeMaxDynamicSharedMemorySize, SMEM_HW);

    // ---- once per call ----
    adj_transpose<<<dim3(NN / 32, NN / 32, BB), 256>>>(adj, p_adjT);
    wT_split<<<dim3(CC / 32, CC / 32, LL), 256>>>(weight, p_wThi, p_wTlo);
    split2<<<(LL * 3 * CC * CC) / 256, 256>>>(w_ih, p_wihhi, p_wihlo);
    split2<<<(LL * 3 * CC * CC) / 256, 256>>>(w_hh, p_whhhi, p_whhlo);
    split2<<<HSZ / 256, 256>>>(x, p_hAhi, p_hAlo);   // h0 = x

    __half* hs_hi[2] = { p_hAhi, p_hBhi };
    __half* hs_lo[2] = { p_hAlo, p_hBlo };

    for (int l = 0; l < LL; l++) {
        __half* chi = hs_hi[l & 1];
        __half* clo = hs_lo[l & 1];
        __half* nhi = hs_hi[(l + 1) & 1];
        __half* nlo = hs_lo[(l + 1) & 1];
        const long loffW = (long)l * CC * CC;
        const long loffG = (long)l * 3 * CC * CC;

        // 1) hwT[d][b*N+j] = sum_c WT[d][c] * h[j][c]   (3-product)
        wmma2_hw<<<dim3(ROWS / 128, 1, 1), 256, SMEM_HW>>>(
            p_wThi + loffW, p_wTlo + loffW, chi, clo,
            p_hwhi, p_hwlo, CC, CC, CC, ROWS);

        // 2) m[b][n][d] = adjT[b] @ (hw_hi + hw_lo)  -> fp16 hi/lo (3-stage pipe)
        adj_mma<<<dim3(1, NN / 256, BB), 256, SMEM_ADJ>>>(
            p_adjT, p_hwhi, p_hwlo, p_mhi, p_mlo,
            NN, NN, ROWS, CC,
            (long)NN * NN, (long)NN, (long)NN * CC);

        // 3+4) gx = (m) @ w_ih^T + b_ih ; gh = (h) @ w_hh^T + b_hh  (merged)
        gate_mma<<<dim3(3, ROWS / 256, 2), 256, SMEM_GATE>>>(
            p_mhi, p_mlo, p_wihhi + loffG, p_wihlo + loffG, p_gx, b_ih + (long)l * 3 * CC,
            chi,   clo,   p_whhhi + loffG, p_whhlo + loffG, p_gh, b_hh + (long)l * 3 * CC);

        // 5) GRU elementwise
        gru_elem3<<<(ROWS * CC) / 256, 256>>>(
            p_gx, p_gh, chi, clo, nhi, nlo, out, mask, (l == LL - 1) ? 1 : 0);
    }
}